// round 1
// baseline (speedup 1.0000x reference)
#include <cuda_runtime.h>

// Problem constants (fixed by reference)
#define BQ 4
#define SQ 2048
#define EMB 1024
#define NHH 16
#define DKK 64
#define BS (BQ*SQ)            // 8192 rows
#define BH (BQ*NHH)           // 64 (b,h) pairs
#define PRED_ELEMS (8388608L)          // BS*EMB
#define ATTN_ELEMS (268435456L)        // BH*SQ*SQ

// Scratch (device globals: sanctioned, no cudaMalloc)
__device__ float g_q[BS*EMB];
__device__ float g_k[BS*EMB];
__device__ float g_v[BS*EMB];
__device__ float g_ph[BS*EMB];
__device__ float g_attn_fb[ATTN_ELEMS];   // fallback if attn not part of d_out
__device__ int   g_mask_mode;             // 0=u8, 1=i32, 2=f32

// ---------------------------------------------------------------------------
// Mask dtype detector: scan first 64KB of raw bytes.
//  - any byte > 1            -> float32 (1.0f contains 0x80/0x3F bytes)
//  - nonzero byte at i%4!=0  -> uint8 (bool)
//  - else                    -> int32
// ---------------------------------------------------------------------------
__global__ void detect_mask_kernel(const unsigned char* __restrict__ m, int nbytes) {
    __shared__ int has_big, has_mis;
    if (threadIdx.x == 0) { has_big = 0; has_mis = 0; }
    __syncthreads();
    int lb = 0, lm = 0;
    for (int i = threadIdx.x; i < nbytes; i += blockDim.x) {
        unsigned char b = m[i];
        if (b > 1) lb = 1;
        else if (b != 0 && (i & 3) != 0) lm = 1;
    }
    if (lb) atomicOr(&has_big, 1);
    if (lm) atomicOr(&has_mis, 1);
    __syncthreads();
    if (threadIdx.x == 0)
        g_mask_mode = has_big ? 2 : (has_mis ? 0 : 1);
}

__device__ __forceinline__ bool mask_at(const char* m, long idx, int mode) {
    if (mode == 0) return ((const unsigned char*)m)[idx] != 0;
    if (mode == 1) return ((const int*)m)[idx] != 0;
    return ((const float*)m)[idx] != 0.0f;
}

// ---------------------------------------------------------------------------
// SGEMM: C[8192,1024] = A[8192,1024] * B[1024,1024]   (fp32)
// BM=128 BN=128 BK=16, 256 threads, 8x8 per thread, float4 everywhere.
// ---------------------------------------------------------------------------
__global__ __launch_bounds__(256) void sgemm_kernel(
    const float* __restrict__ A, const float* __restrict__ B, float* __restrict__ C)
{
    const int N = 1024, K = 1024;
    __shared__ float As[16][132];   // [k][m], padded
    __shared__ float Bs[16][132];   // [k][n], padded

    int tid = threadIdx.x;
    int bm = blockIdx.y * 128;
    int bn = blockIdx.x * 128;
    int tx = tid & 15, ty = tid >> 4;

    float acc[8][8];
#pragma unroll
    for (int i = 0; i < 8; i++)
#pragma unroll
        for (int j = 0; j < 8; j++) acc[i][j] = 0.0f;

    for (int k0 = 0; k0 < K; k0 += 16) {
        float4 a4[2], b4[2];
#pragma unroll
        for (int l = 0; l < 2; l++) {
            int idx = tid + 256 * l;
            int ar = idx >> 2, ak = (idx & 3) << 2;
            a4[l] = *(const float4*)&A[(long)(bm + ar) * K + k0 + ak];
            int br = idx >> 5, bn2 = (idx & 31) << 2;
            b4[l] = *(const float4*)&B[(long)(k0 + br) * N + bn + bn2];
        }
        __syncthreads();
#pragma unroll
        for (int l = 0; l < 2; l++) {
            int idx = tid + 256 * l;
            int ar = idx >> 2, ak = (idx & 3) << 2;
            As[ak + 0][ar] = a4[l].x; As[ak + 1][ar] = a4[l].y;
            As[ak + 2][ar] = a4[l].z; As[ak + 3][ar] = a4[l].w;
            int br = idx >> 5, bn2 = (idx & 31) << 2;
            *(float4*)&Bs[br][bn2] = b4[l];
        }
        __syncthreads();
#pragma unroll
        for (int kk = 0; kk < 16; kk++) {
            float a[8], b[8];
            *(float4*)&a[0] = *(float4*)&As[kk][ty * 8];
            *(float4*)&a[4] = *(float4*)&As[kk][ty * 8 + 4];
            *(float4*)&b[0] = *(float4*)&Bs[kk][tx * 8];
            *(float4*)&b[4] = *(float4*)&Bs[kk][tx * 8 + 4];
#pragma unroll
            for (int i = 0; i < 8; i++)
#pragma unroll
                for (int j = 0; j < 8; j++) acc[i][j] += a[i] * b[j];
        }
    }

#pragma unroll
    for (int i = 0; i < 8; i++) {
        long row = (long)(bm + ty * 8 + i) * N + bn + tx * 8;
        *(float4*)&C[row]     = *(float4*)&acc[i][0];
        *(float4*)&C[row + 4] = *(float4*)&acc[i][4];
    }
}

// ---------------------------------------------------------------------------
// Scores: attn_raw[b,h,q,k] = mask ? -1e9 : (q . k)/8
// q,k layout: [b, s, h*64+d]. Per block: 64q x 64k tile, full D=64 in smem.
// ---------------------------------------------------------------------------
__global__ __launch_bounds__(256) void scores_kernel(
    const float* __restrict__ q, const float* __restrict__ k,
    const char* __restrict__ mask, float* __restrict__ attn)
{
    int bh = blockIdx.z;
    int b = bh / NHH, h = bh % NHH;
    int q0 = blockIdx.y * 64;
    int k0 = blockIdx.x * 64;

    __shared__ float Qs[64][68];   // [d][m]
    __shared__ float Ks[64][68];   // [d][n]

    int tid = threadIdx.x;
#pragma unroll
    for (int l = 0; l < 4; l++) {
        int idx = tid + 256 * l;            // 0..1023 float4 slots
        int row = idx >> 4;                 // 0..63
        int dq = (idx & 15) << 2;           // 0..60
        float4 v4 = *(const float4*)&q[((long)(b * SQ + q0 + row)) * EMB + h * DKK + dq];
        Qs[dq + 0][row] = v4.x; Qs[dq + 1][row] = v4.y;
        Qs[dq + 2][row] = v4.z; Qs[dq + 3][row] = v4.w;
        float4 w4 = *(const float4*)&k[((long)(b * SQ + k0 + row)) * EMB + h * DKK + dq];
        Ks[dq + 0][row] = w4.x; Ks[dq + 1][row] = w4.y;
        Ks[dq + 2][row] = w4.z; Ks[dq + 3][row] = w4.w;
    }
    __syncthreads();

    int tx = tid & 15, ty = tid >> 4;
    float acc[4][4];
#pragma unroll
    for (int i = 0; i < 4; i++)
#pragma unroll
        for (int j = 0; j < 4; j++) acc[i][j] = 0.0f;

#pragma unroll
    for (int d = 0; d < 64; d++) {
        float4 a = *(float4*)&Qs[d][ty * 4];
        float4 bb = *(float4*)&Ks[d][tx * 4];
        float av[4] = {a.x, a.y, a.z, a.w};
        float bv[4] = {bb.x, bb.y, bb.z, bb.w};
#pragma unroll
        for (int i = 0; i < 4; i++)
#pragma unroll
            for (int j = 0; j < 4; j++) acc[i][j] += av[i] * bv[j];
    }

    int mode = g_mask_mode;
#pragma unroll
    for (int i = 0; i < 4; i++) {
        int qi = q0 + ty * 4 + i;
        long mrow = ((long)b * SQ + qi) * SQ;
        float* orow = &attn[(((long)bh) * SQ + qi) * SQ];
#pragma unroll
        for (int j = 0; j < 4; j++) {
            int kj = k0 + tx * 4 + j;
            bool msk = mask_at(mask, mrow + kj, mode);
            orow[kj] = msk ? -1e9f : acc[i][j] * 0.125f;
        }
    }
}

// ---------------------------------------------------------------------------
// Row softmax in place over rows of length 2048. One block per row.
// ---------------------------------------------------------------------------
__device__ __forceinline__ float warpMax(float v) {
#pragma unroll
    for (int o = 16; o; o >>= 1) v = fmaxf(v, __shfl_xor_sync(0xFFFFFFFFu, v, o));
    return v;
}
__device__ __forceinline__ float warpSum(float v) {
#pragma unroll
    for (int o = 16; o; o >>= 1) v += __shfl_xor_sync(0xFFFFFFFFu, v, o);
    return v;
}

__global__ __launch_bounds__(256) void softmax_kernel(float* __restrict__ attn)
{
    long row = blockIdx.x;
    float* p = attn + row * SQ;
    int tid = threadIdx.x;

    float4 v0 = *(float4*)&p[tid * 4];
    float4 v1 = *(float4*)&p[1024 + tid * 4];

    float m = fmaxf(fmaxf(fmaxf(v0.x, v0.y), fmaxf(v0.z, v0.w)),
                    fmaxf(fmaxf(v1.x, v1.y), fmaxf(v1.z, v1.w)));
    m = warpMax(m);
    __shared__ float red[8];
    int wid = tid >> 5, lane = tid & 31;
    if (lane == 0) red[wid] = m;
    __syncthreads();
    float bm = -3.4e38f;
#pragma unroll
    for (int i = 0; i < 8; i++) bm = fmaxf(bm, red[i]);

    float4 e0, e1;
    e0.x = __expf(v0.x - bm); e0.y = __expf(v0.y - bm);
    e0.z = __expf(v0.z - bm); e0.w = __expf(v0.w - bm);
    e1.x = __expf(v1.x - bm); e1.y = __expf(v1.y - bm);
    e1.z = __expf(v1.z - bm); e1.w = __expf(v1.w - bm);

    float s = (e0.x + e0.y + e0.z + e0.w) + (e1.x + e1.y + e1.z + e1.w);
    s = warpSum(s);
    __syncthreads();
    if (lane == 0) red[wid] = s;
    __syncthreads();
    float bs = 0.0f;
#pragma unroll
    for (int i = 0; i < 8; i++) bs += red[i];
    float inv = 1.0f / bs;

    e0.x *= inv; e0.y *= inv; e0.z *= inv; e0.w *= inv;
    e1.x *= inv; e1.y *= inv; e1.z *= inv; e1.w *= inv;
    *(float4*)&p[tid * 4] = e0;
    *(float4*)&p[1024 + tid * 4] = e1;
}

// ---------------------------------------------------------------------------
// PV: ph[b,q,h*64+d] = sum_k attn[b,h,q,k] * v[b,k,h*64+d]
// Per block: 128 q-rows x full D=64, K tiled by 16.
// ---------------------------------------------------------------------------
__global__ __launch_bounds__(256) void pv_kernel(
    const float* __restrict__ attn, const float* __restrict__ v, float* __restrict__ ph)
{
    int bh = blockIdx.y;
    int b = bh / NHH, h = bh % NHH;
    int m0 = blockIdx.x * 128;

    __shared__ float As[16][132];  // [k][m]
    __shared__ float Vs[16][68];   // [k][d]

    int tid = threadIdx.x;
    int tx = tid & 15, ty = tid >> 4;

    float acc[8][4];
#pragma unroll
    for (int i = 0; i < 8; i++)
#pragma unroll
        for (int j = 0; j < 4; j++) acc[i][j] = 0.0f;

    const long attn_base = ((long)bh) * SQ * SQ;

    for (int k0 = 0; k0 < SQ; k0 += 16) {
        float4 a4[2];
#pragma unroll
        for (int l = 0; l < 2; l++) {
            int idx = tid + 256 * l;
            int ar = idx >> 2, ak = (idx & 3) << 2;
            a4[l] = *(const float4*)&attn[attn_base + (long)(m0 + ar) * SQ + k0 + ak];
        }
        int vr = tid >> 4, vn = (tid & 15) << 2;
        float4 v4 = *(const float4*)&v[((long)(b * SQ + k0 + vr)) * EMB + h * DKK + vn];

        __syncthreads();
#pragma unroll
        for (int l = 0; l < 2; l++) {
            int idx = tid + 256 * l;
            int ar = idx >> 2, ak = (idx & 3) << 2;
            As[ak + 0][ar] = a4[l].x; As[ak + 1][ar] = a4[l].y;
            As[ak + 2][ar] = a4[l].z; As[ak + 3][ar] = a4[l].w;
        }
        *(float4*)&Vs[vr][vn] = v4;
        __syncthreads();

#pragma unroll
        for (int kk = 0; kk < 16; kk++) {
            float a[8];
            *(float4*)&a[0] = *(float4*)&As[kk][ty * 8];
            *(float4*)&a[4] = *(float4*)&As[kk][ty * 8 + 4];
            float4 bb = *(float4*)&Vs[kk][tx * 4];
            float bv[4] = {bb.x, bb.y, bb.z, bb.w};
#pragma unroll
            for (int i = 0; i < 8; i++)
#pragma unroll
                for (int j = 0; j < 4; j++) acc[i][j] += a[i] * bv[j];
        }
    }

#pragma unroll
    for (int i = 0; i < 8; i++) {
        long o = ((long)(b * SQ + m0 + ty * 8 + i)) * EMB + h * DKK + tx * 4;
        *(float4*)&ph[o] = *(float4*)&acc[i][0];
    }
}

// ---------------------------------------------------------------------------
extern "C" void kernel_launch(void* const* d_in, const int* in_sizes, int n_in,
                              void* d_out, int out_size)
{
    const float* Q   = (const float*)d_in[0];
    const float* K   = (const float*)d_in[1];
    const float* V   = (const float*)d_in[2];
    const char*  msk = (const char*)d_in[3];
    const float* WQ  = (const float*)d_in[4];
    const float* WK  = (const float*)d_in[5];
    const float* WV  = (const float*)d_in[6];
    const float* Wfc = (const float*)d_in[7];
    float* out = (float*)d_out;

    float *pq, *pk, *pv, *pph, *pfb;
    cudaGetSymbolAddress((void**)&pq,  g_q);
    cudaGetSymbolAddress((void**)&pk,  g_k);
    cudaGetSymbolAddress((void**)&pv,  g_v);
    cudaGetSymbolAddress((void**)&pph, g_ph);
    cudaGetSymbolAddress((void**)&pfb, g_attn_fb);

    float* attnbuf = ((long)out_size >= PRED_ELEMS + ATTN_ELEMS)
                         ? (out + PRED_ELEMS) : pfb;

    detect_mask_kernel<<<1, 256>>>((const unsigned char*)msk, 65536);

    dim3 gg(1024 / 128, BS / 128);
    sgemm_kernel<<<gg, 256>>>(Q, WQ, pq);
    sgemm_kernel<<<gg, 256>>>(K, WK, pk);
    sgemm_kernel<<<gg, 256>>>(V, WV, pv);

    scores_kernel<<<dim3(SQ / 64, SQ / 64, BH), 256>>>(pq, pk, msk, attnbuf);
    softmax_kernel<<<BH * SQ, 256>>>(attnbuf);
    pv_kernel<<<dim3(SQ / 128, BH), 256>>>(attnbuf, pv, pph);

    sgemm_kernel<<<gg, 256>>>(pph, Wfc, out);
}

// round 4
// speedup vs baseline: 1.2327x; 1.2327x over previous
#include <cuda_runtime.h>
#include <cuda_bf16.h>
#include <cstdint>

// Problem constants (fixed by reference)
#define BQ 4
#define SQ 2048
#define EMB 1024
#define NHH 16
#define DKK 64
#define BS (BQ*SQ)            // 8192 rows
#define BH (BQ*NHH)           // 64 (b,h) pairs
#define PRED_ELEMS (8388608L)          // BS*EMB
#define ATTN_ELEMS (268435456L)        // BH*SQ*SQ

// Scratch (device globals: sanctioned, no cudaMalloc)
__device__ float g_q[BS*EMB];
__device__ float g_k[BS*EMB];
__device__ float g_v[BS*EMB];
__device__ float g_ph[BS*EMB];
__device__ float g_attn_fb[ATTN_ELEMS];   // fallback if attn not part of d_out
__device__ int   g_mask_mode;             // 0=u8, 1=i32, 2=f32

// bf16 split buffers (reused serially across the 4 GEMMs)
__device__ __nv_bfloat16 g_ah[BS*EMB];    // A hi   [M][K]
__device__ __nv_bfloat16 g_al[BS*EMB];    // A lo
__device__ __nv_bfloat16 g_bhT[EMB*EMB];  // B hi, TRANSPOSED: [N][K]
__device__ __nv_bfloat16 g_blT[EMB*EMB];  // B lo, TRANSPOSED

// ---------------------------------------------------------------------------
// Helpers
// ---------------------------------------------------------------------------
__device__ __forceinline__ uint32_t smem_u32(const void* p) {
    uint32_t a;
    asm("{ .reg .u64 t; cvta.to.shared.u64 t, %1; cvt.u32.u64 %0, t; }" : "=r"(a) : "l"(p));
    return a;
}
__device__ __forceinline__ void cp16(uint32_t dst, const void* src) {
    asm volatile("cp.async.cg.shared.global [%0], [%1], 16;" :: "r"(dst), "l"(src));
}
__device__ __forceinline__ void cp_commit() {
    asm volatile("cp.async.commit_group;" ::: "memory");
}
template<int N> __device__ __forceinline__ void cp_wait() {
    asm volatile("cp.async.wait_group %0;" :: "n"(N) : "memory");
}
__device__ __forceinline__ void mma16816(float* c,
    uint32_t a0, uint32_t a1, uint32_t a2, uint32_t a3, uint32_t b0, uint32_t b1) {
    asm volatile(
        "mma.sync.aligned.m16n8k16.row.col.f32.bf16.bf16.f32 "
        "{%0,%1,%2,%3}, {%4,%5,%6,%7}, {%8,%9}, {%0,%1,%2,%3};"
        : "+f"(c[0]), "+f"(c[1]), "+f"(c[2]), "+f"(c[3])
        : "r"(a0), "r"(a1), "r"(a2), "r"(a3), "r"(b0), "r"(b1));
}

// ---------------------------------------------------------------------------
// Mask dtype detector
// ---------------------------------------------------------------------------
__global__ void detect_mask_kernel(const unsigned char* __restrict__ m, int nbytes) {
    __shared__ int has_big, has_mis;
    if (threadIdx.x == 0) { has_big = 0; has_mis = 0; }
    __syncthreads();
    int lb = 0, lm = 0;
    for (int i = threadIdx.x; i < nbytes; i += blockDim.x) {
        unsigned char b = m[i];
        if (b > 1) lb = 1;
        else if (b != 0 && (i & 3) != 0) lm = 1;
    }
    if (lb) atomicOr(&has_big, 1);
    if (lm) atomicOr(&has_mis, 1);
    __syncthreads();
    if (threadIdx.x == 0)
        g_mask_mode = has_big ? 2 : (has_mis ? 0 : 1);
}

__device__ __forceinline__ bool mask_at(const char* m, long idx, int mode) {
    if (mode == 0) return ((const unsigned char*)m)[idx] != 0;
    if (mode == 1) return ((const int*)m)[idx] != 0;
    return ((const float*)m)[idx] != 0.0f;
}

// ---------------------------------------------------------------------------
// fp32 -> bf16 (hi, lo) elementwise split.
// ---------------------------------------------------------------------------
__global__ __launch_bounds__(256) void conv_split_kernel(
    const float* __restrict__ in, __nv_bfloat16* __restrict__ hi,
    __nv_bfloat16* __restrict__ lo, long n)
{
    long i = ((long)blockIdx.x * blockDim.x + threadIdx.x) * 4;
    if (i >= n) return;
    float4 a = *(const float4*)&in[i];
    float av[4] = {a.x, a.y, a.z, a.w};
    ushort4 hv, lv;
    unsigned short* hp = &hv.x; unsigned short* lp = &lv.x;
#pragma unroll
    for (int j = 0; j < 4; j++) {
        __nv_bfloat16 h = __float2bfloat16_rn(av[j]);
        __nv_bfloat16 l = __float2bfloat16_rn(av[j] - __bfloat162float(h));
        hp[j] = *(unsigned short*)&h;
        lp[j] = *(unsigned short*)&l;
    }
    *(ushort4*)&hi[i] = hv;
    *(ushort4*)&lo[i] = lv;
}

// ---------------------------------------------------------------------------
// Weight transpose + split: W[K=1024][N=1024] fp32 -> hiT/loT [N][K] bf16
// ---------------------------------------------------------------------------
__global__ __launch_bounds__(256) void conv_transpose_kernel(
    const float* __restrict__ W, __nv_bfloat16* __restrict__ hiT,
    __nv_bfloat16* __restrict__ loT)
{
    __shared__ float tile[32][33];
    int kb = blockIdx.y * 32, nb = blockIdx.x * 32;
    int tx = threadIdx.x & 31, ty = threadIdx.x >> 5;   // ty 0..7
#pragma unroll
    for (int r = 0; r < 4; r++) {
        int kk = ty * 4 + r;
        tile[kk][tx] = W[(long)(kb + kk) * EMB + nb + tx];
    }
    __syncthreads();
#pragma unroll
    for (int r = 0; r < 4; r++) {
        int nn = ty * 4 + r;
        float v = tile[tx][nn];
        __nv_bfloat16 h = __float2bfloat16_rn(v);
        __nv_bfloat16 l = __float2bfloat16_rn(v - __bfloat162float(h));
        long o = (long)(nb + nn) * EMB + kb + tx;
        hiT[o] = h;
        loT[o] = l;
    }
}

// ---------------------------------------------------------------------------
// Split-bf16 HMMA GEMM: C[M][1024] = A[M][1024] * B[1024][1024]
// A as (Ah, Al) [M][K]; B as (BhT, BlT) [N][K].
// D += Ah*Bh + Ah*Bl + Al*Bh   (lo*lo dropped: ~2^-18 relative)
// Tile 128x128, BK=32, 8 warps (2x4), warp tile 64x32, m16n8k16 mma.
// SMEM rows padded to 40 bf16 (80B) for conflict-free quad loads.
// ---------------------------------------------------------------------------
#define GBK 32
#define GKSTEPS (EMB / GBK)      // 32
#define ROWP 40                  // padded row length (bf16 elems)
#define MAT_BYTES (128 * ROWP * 2)   // 10240
#define OA_H 0
#define OA_L (MAT_BYTES)
#define OB_H (2 * MAT_BYTES)
#define OB_L (3 * MAT_BYTES)
#define STG (4 * MAT_BYTES)          // 40960
#define GEMM_SMEM (2 * STG)          // 81920

__global__ __launch_bounds__(256, 1) void gemm_mma_kernel(
    const __nv_bfloat16* __restrict__ Ah, const __nv_bfloat16* __restrict__ Al,
    const __nv_bfloat16* __restrict__ BhT, const __nv_bfloat16* __restrict__ BlT,
    float* __restrict__ C)
{
    extern __shared__ char smem[];
    uint32_t sb = smem_u32(smem);

    const int tid = threadIdx.x;
    const int wid = tid >> 5;
    const int lane = tid & 31;
    const int wm = wid >> 2;          // 0..1  (64-row slab)
    const int wn = wid & 3;           // 0..3  (32-col slab)
    const int bm = blockIdx.y * 128;
    const int bn = blockIdx.x * 128;

    const int lr = lane >> 2;         // 0..7
    const int lc = (lane & 3) * 2;    // 0,2,4,6

    float acc[4][4][4];
#pragma unroll
    for (int i = 0; i < 4; i++)
#pragma unroll
        for (int j = 0; j < 4; j++)
#pragma unroll
            for (int v = 0; v < 4; v++) acc[i][j][v] = 0.0f;

    // Stage loader: 512 16B chunks per matrix, 2 per thread.
    auto load_stage = [&](int s, int k0) {
        uint32_t base = sb + s * STG;
#pragma unroll
        for (int c = 0; c < 2; c++) {
            int ch = tid + c * 256;           // 0..511
            int row = ch >> 2, j = ch & 3;    // row 0..127, 16B chunk 0..3
            uint32_t soff = (uint32_t)(row * 80 + j * 16);
            long ga = (long)(bm + row) * EMB + k0 + j * 8;
            long gb = (long)(bn + row) * EMB + k0 + j * 8;
            cp16(base + OA_H + soff, Ah + ga);
            cp16(base + OA_L + soff, Al + ga);
            cp16(base + OB_H + soff, BhT + gb);
            cp16(base + OB_L + soff, BlT + gb);
        }
        cp_commit();
    };

    load_stage(0, 0);

    for (int t = 0; t < GKSTEPS; t++) {
        int s = t & 1;
        if (t + 1 < GKSTEPS) {
            load_stage(s ^ 1, (t + 1) * GBK);
            cp_wait<1>();
        } else {
            cp_wait<0>();
        }
        __syncthreads();

        const char* st = smem + s * STG;
#pragma unroll
        for (int ks = 0; ks < 2; ks++) {
            int kb = ks * 16;
            // B fragments (hi & lo) for the 4 n-tiles
            uint32_t bh[4][2], bl[4][2];
#pragma unroll
            for (int ni = 0; ni < 4; ni++) {
                int n = wn * 32 + ni * 8 + lr;
                int k = kb + lc;
                const char* ph = st + OB_H + (n * ROWP + k) * 2;
                const char* pl = st + OB_L + (n * ROWP + k) * 2;
                bh[ni][0] = *(const uint32_t*)ph;
                bh[ni][1] = *(const uint32_t*)(ph + 16);
                bl[ni][0] = *(const uint32_t*)pl;
                bl[ni][1] = *(const uint32_t*)(pl + 16);
            }
#pragma unroll
            for (int mi = 0; mi < 4; mi++) {
                int m = wm * 64 + mi * 16 + lr;
                int k = kb + lc;
                const char* ph = st + OA_H + (m * ROWP + k) * 2;
                const char* pl = st + OA_L + (m * ROWP + k) * 2;
                uint32_t ah0 = *(const uint32_t*)ph;
                uint32_t ah1 = *(const uint32_t*)(ph + 8 * ROWP * 2);
                uint32_t ah2 = *(const uint32_t*)(ph + 16);
                uint32_t ah3 = *(const uint32_t*)(ph + 8 * ROWP * 2 + 16);
                uint32_t al0 = *(const uint32_t*)pl;
                uint32_t al1 = *(const uint32_t*)(pl + 8 * ROWP * 2);
                uint32_t al2 = *(const uint32_t*)(pl + 16);
                uint32_t al3 = *(const uint32_t*)(pl + 8 * ROWP * 2 + 16);
#pragma unroll
                for (int ni = 0; ni < 4; ni++) {
                    mma16816(acc[mi][ni], ah0, ah1, ah2, ah3, bh[ni][0], bh[ni][1]);
                    mma16816(acc[mi][ni], ah0, ah1, ah2, ah3, bl[ni][0], bl[ni][1]);
                    mma16816(acc[mi][ni], al0, al1, al2, al3, bh[ni][0], bh[ni][1]);
                }
            }
        }
        __syncthreads();
    }

    // Epilogue
#pragma unroll
    for (int mi = 0; mi < 4; mi++) {
#pragma unroll
        for (int ni = 0; ni < 4; ni++) {
            int r = bm + wm * 64 + mi * 16 + lr;
            int cc = bn + wn * 32 + ni * 8 + lc;
            float2 v0 = {acc[mi][ni][0], acc[mi][ni][1]};
            float2 v1 = {acc[mi][ni][2], acc[mi][ni][3]};
            *(float2*)&C[(long)r * EMB + cc] = v0;
            *(float2*)&C[(long)(r + 8) * EMB + cc] = v1;
        }
    }
}

// ---------------------------------------------------------------------------
// Scores: attn_raw[b,h,q,k] = mask ? -1e9 : (q . k)/8
// ---------------------------------------------------------------------------
__global__ __launch_bounds__(256) void scores_kernel(
    const float* __restrict__ q, const float* __restrict__ k,
    const char* __restrict__ mask, float* __restrict__ attn)
{
    int bh = blockIdx.z;
    int b = bh / NHH, h = bh % NHH;
    int q0 = blockIdx.y * 64;
    int k0 = blockIdx.x * 64;

    __shared__ float Qs[64][68];
    __shared__ float Ks[64][68];

    int tid = threadIdx.x;
#pragma unroll
    for (int l = 0; l < 4; l++) {
        int idx = tid + 256 * l;
        int row = idx >> 4;
        int dq = (idx & 15) << 2;
        float4 v4 = *(const float4*)&q[((long)(b * SQ + q0 + row)) * EMB + h * DKK + dq];
        Qs[dq + 0][row] = v4.x; Qs[dq + 1][row] = v4.y;
        Qs[dq + 2][row] = v4.z; Qs[dq + 3][row] = v4.w;
        float4 w4 = *(const float4*)&k[((long)(b * SQ + k0 + row)) * EMB + h * DKK + dq];
        Ks[dq + 0][row] = w4.x; Ks[dq + 1][row] = w4.y;
        Ks[dq + 2][row] = w4.z; Ks[dq + 3][row] = w4.w;
    }
    __syncthreads();

    int tx = tid & 15, ty = tid >> 4;
    float acc[4][4];
#pragma unroll
    for (int i = 0; i < 4; i++)
#pragma unroll
        for (int j = 0; j < 4; j++) acc[i][j] = 0.0f;

#pragma unroll
    for (int d = 0; d < 64; d++) {
        float4 a = *(float4*)&Qs[d][ty * 4];
        float4 bb = *(float4*)&Ks[d][tx * 4];
        float av[4] = {a.x, a.y, a.z, a.w};
        float bv[4] = {bb.x, bb.y, bb.z, bb.w};
#pragma unroll
        for (int i = 0; i < 4; i++)
#pragma unroll
            for (int j = 0; j < 4; j++) acc[i][j] += av[i] * bv[j];
    }

    int mode = g_mask_mode;
#pragma unroll
    for (int i = 0; i < 4; i++) {
        int qi = q0 + ty * 4 + i;
        long mrow = ((long)b * SQ + qi) * SQ;
        float* orow = &attn[(((long)bh) * SQ + qi) * SQ];
#pragma unroll
        for (int j = 0; j < 4; j++) {
            int kj = k0 + tx * 4 + j;
            bool msk = mask_at(mask, mrow + kj, mode);
            orow[kj] = msk ? -1e9f : acc[i][j] * 0.125f;
        }
    }
}

// ---------------------------------------------------------------------------
// Row softmax in place over rows of length 2048.
// ---------------------------------------------------------------------------
__device__ __forceinline__ float warpMax(float v) {
#pragma unroll
    for (int o = 16; o; o >>= 1) v = fmaxf(v, __shfl_xor_sync(0xFFFFFFFFu, v, o));
    return v;
}
__device__ __forceinline__ float warpSum(float v) {
#pragma unroll
    for (int o = 16; o; o >>= 1) v += __shfl_xor_sync(0xFFFFFFFFu, v, o);
    return v;
}

__global__ __launch_bounds__(256) void softmax_kernel(float* __restrict__ attn)
{
    long row = blockIdx.x;
    float* p = attn + row * SQ;
    int tid = threadIdx.x;

    float4 v0 = *(float4*)&p[tid * 4];
    float4 v1 = *(float4*)&p[1024 + tid * 4];

    float m = fmaxf(fmaxf(fmaxf(v0.x, v0.y), fmaxf(v0.z, v0.w)),
                    fmaxf(fmaxf(v1.x, v1.y), fmaxf(v1.z, v1.w)));
    m = warpMax(m);
    __shared__ float red[8];
    int wid = tid >> 5, lane = tid & 31;
    if (lane == 0) red[wid] = m;
    __syncthreads();
    float bm = -3.4e38f;
#pragma unroll
    for (int i = 0; i < 8; i++) bm = fmaxf(bm, red[i]);

    float4 e0, e1;
    e0.x = __expf(v0.x - bm); e0.y = __expf(v0.y - bm);
    e0.z = __expf(v0.z - bm); e0.w = __expf(v0.w - bm);
    e1.x = __expf(v1.x - bm); e1.y = __expf(v1.y - bm);
    e1.z = __expf(v1.z - bm); e1.w = __expf(v1.w - bm);

    float s = (e0.x + e0.y + e0.z + e0.w) + (e1.x + e1.y + e1.z + e1.w);
    s = warpSum(s);
    __syncthreads();
    if (lane == 0) red[wid] = s;
    __syncthreads();
    float bs = 0.0f;
#pragma unroll
    for (int i = 0; i < 8; i++) bs += red[i];
    float inv = 1.0f / bs;

    e0.x *= inv; e0.y *= inv; e0.z *= inv; e0.w *= inv;
    e1.x *= inv; e1.y *= inv; e1.z *= inv; e1.w *= inv;
    *(float4*)&p[tid * 4] = e0;
    *(float4*)&p[1024 + tid * 4] = e1;
}

// ---------------------------------------------------------------------------
// PV: ph[b,q,h*64+d] = sum_k attn[b,h,q,k] * v[b,k,h*64+d]
// ---------------------------------------------------------------------------
__global__ __launch_bounds__(256) void pv_kernel(
    const float* __restrict__ attn, const float* __restrict__ v, float* __restrict__ ph)
{
    int bh = blockIdx.y;
    int b = bh / NHH, h = bh % NHH;
    int m0 = blockIdx.x * 128;

    __shared__ float As[16][132];
    __shared__ float Vs[16][68];

    int tid = threadIdx.x;
    int tx = tid & 15, ty = tid >> 4;

    float acc[8][4];
#pragma unroll
    for (int i = 0; i < 8; i++)
#pragma unroll
        for (int j = 0; j < 4; j++) acc[i][j] = 0.0f;

    const long attn_base = ((long)bh) * SQ * SQ;

    for (int k0 = 0; k0 < SQ; k0 += 16) {
        float4 a4[2];
#pragma unroll
        for (int l = 0; l < 2; l++) {
            int idx = tid + 256 * l;
            int ar = idx >> 2, ak = (idx & 3) << 2;
            a4[l] = *(const float4*)&attn[attn_base + (long)(m0 + ar) * SQ + k0 + ak];
        }
        int vr = tid >> 4, vn = (tid & 15) << 2;
        float4 v4 = *(const float4*)&v[((long)(b * SQ + k0 + vr)) * EMB + h * DKK + vn];

        __syncthreads();
#pragma unroll
        for (int l = 0; l < 2; l++) {
            int idx = tid + 256 * l;
            int ar = idx >> 2, ak = (idx & 3) << 2;
            As[ak + 0][ar] = a4[l].x; As[ak + 1][ar] = a4[l].y;
            As[ak + 2][ar] = a4[l].z; As[ak + 3][ar] = a4[l].w;
        }
        *(float4*)&Vs[vr][vn] = v4;
        __syncthreads();

#pragma unroll
        for (int kk = 0; kk < 16; kk++) {
            float a[8];
            *(float4*)&a[0] = *(float4*)&As[kk][ty * 8];
            *(float4*)&a[4] = *(float4*)&As[kk][ty * 8 + 4];
            float4 bb = *(float4*)&Vs[kk][tx * 4];
            float bv[4] = {bb.x, bb.y, bb.z, bb.w};
#pragma unroll
            for (int i = 0; i < 8; i++)
#pragma unroll
                for (int j = 0; j < 4; j++) acc[i][j] += a[i] * bv[j];
        }
    }

#pragma unroll
    for (int i = 0; i < 8; i++) {
        long o = ((long)(b * SQ + m0 + ty * 8 + i)) * EMB + h * DKK + tx * 4;
        *(float4*)&ph[o] = *(float4*)&acc[i][0];
    }
}

// ---------------------------------------------------------------------------
extern "C" void kernel_launch(void* const* d_in, const int* in_sizes, int n_in,
                              void* d_out, int out_size)
{
    const float* Q   = (const float*)d_in[0];
    const float* K   = (const float*)d_in[1];
    const float* V   = (const float*)d_in[2];
    const char*  msk = (const char*)d_in[3];
    const float* WQ  = (const float*)d_in[4];
    const float* WK  = (const float*)d_in[5];
    const float* WV  = (const float*)d_in[6];
    const float* Wfc = (const float*)d_in[7];
    float* out = (float*)d_out;

    float *pq, *pk, *pv, *pph, *pfb;
    __nv_bfloat16 *pah, *pal, *pbh, *pbl;
    cudaGetSymbolAddress((void**)&pq,  g_q);
    cudaGetSymbolAddress((void**)&pk,  g_k);
    cudaGetSymbolAddress((void**)&pv,  g_v);
    cudaGetSymbolAddress((void**)&pph, g_ph);
    cudaGetSymbolAddress((void**)&pfb, g_attn_fb);
    cudaGetSymbolAddress((void**)&pah, g_ah);
    cudaGetSymbolAddress((void**)&pal, g_al);
    cudaGetSymbolAddress((void**)&pbh, g_bhT);
    cudaGetSymbolAddress((void**)&pbl, g_blT);

    float* attnbuf = ((long)out_size >= PRED_ELEMS + ATTN_ELEMS)
                         ? (out + PRED_ELEMS) : pfb;

    cudaFuncSetAttribute(gemm_mma_kernel,
                         cudaFuncAttributeMaxDynamicSharedMemorySize, GEMM_SMEM);

    detect_mask_kernel<<<1, 256>>>((const unsigned char*)msk, 65536);

    const long AN = (long)BS * EMB;
    dim3 cg((unsigned)((AN / 4 + 255) / 256));
    dim3 tg(EMB / 32, EMB / 32);
    dim3 gg(EMB / 128, BS / 128);

    // Q projection
    conv_split_kernel<<<cg, 256>>>(Q, pah, pal, AN);
    conv_transpose_kernel<<<tg, 256>>>(WQ, pbh, pbl);
    gemm_mma_kernel<<<gg, 256, GEMM_SMEM>>>(pah, pal, pbh, pbl, pq);
    // K projection
    conv_split_kernel<<<cg, 256>>>(K, pah, pal, AN);
    conv_transpose_kernel<<<tg, 256>>>(WK, pbh, pbl);
    gemm_mma_kernel<<<gg, 256, GEMM_SMEM>>>(pah, pal, pbh, pbl, pk);
    // V projection
    conv_split_kernel<<<cg, 256>>>(V, pah, pal, AN);
    conv_transpose_kernel<<<tg, 256>>>(WV, pbh, pbl);
    gemm_mma_kernel<<<gg, 256, GEMM_SMEM>>>(pah, pal, pbh, pbl, pv);

    // attention
    scores_kernel<<<dim3(SQ / 64, SQ / 64, BH), 256>>>(pq, pk, msk, attnbuf);
    softmax_kernel<<<BH * SQ, 256>>>(attnbuf);
    pv_kernel<<<dim3(SQ / 128, BH), 256>>>(attnbuf, pv, pph);

    // output projection
    conv_split_kernel<<<cg, 256>>>(pph, pah, pal, AN);
    conv_transpose_kernel<<<tg, 256>>>(Wfc, pbh, pbl);
    gemm_mma_kernel<<<gg, 256, GEMM_SMEM>>>(pah, pal, pbh, pbl, out);
}

// round 5
// speedup vs baseline: 1.7553x; 1.4240x over previous
#include <cuda_runtime.h>
#include <cuda_bf16.h>
#include <cstdint>

// Problem constants (fixed by reference)
#define BQ 4
#define SQ 2048
#define EMB 1024
#define NHH 16
#define DKK 64
#define BS (BQ*SQ)            // 8192 rows
#define BH (BQ*NHH)           // 64 (b,h) pairs
#define PRED_ELEMS (8388608L)          // BS*EMB
#define ATTN_ELEMS (268435456L)        // BH*SQ*SQ
#define MASK_ELEMS (16777216L)         // BQ*SQ*SQ

// Scratch (device globals: sanctioned, no cudaMalloc)
__device__ float g_q[BS*EMB];
__device__ float g_k[BS*EMB];
__device__ float g_v[BS*EMB];
__device__ float g_ph[BS*EMB];
__device__ float g_attn_fb[ATTN_ELEMS];   // fallback if attn not part of d_out
__device__ int   g_mask_mode;             // 0=u8, 1=i32, 2=f32

// bf16 split buffers
__device__ __nv_bfloat16 g_ah[BS*EMB];    // GEMM A hi   [M][K]
__device__ __nv_bfloat16 g_al[BS*EMB];    // GEMM A lo
__device__ __nv_bfloat16 g_bhT[EMB*EMB];  // GEMM B hi, transposed [N][K]
__device__ __nv_bfloat16 g_blT[EMB*EMB];  // GEMM B lo
__device__ __nv_bfloat16 g_qh[BS*EMB];    // q hi/lo [b,s,emb]
__device__ __nv_bfloat16 g_ql[BS*EMB];
__device__ __nv_bfloat16 g_kh[BS*EMB];    // k hi/lo
__device__ __nv_bfloat16 g_kl[BS*EMB];
__device__ __nv_bfloat16 g_vth[BH*DKK*SQ]; // v hi/lo transposed per head: [(bh)*64+d][s]
__device__ __nv_bfloat16 g_vtl[BH*DKK*SQ];
__device__ unsigned char g_mask8[MASK_ELEMS];  // canonical u8 mask

// ---------------------------------------------------------------------------
// Helpers
// ---------------------------------------------------------------------------
__device__ __forceinline__ uint32_t smem_u32(const void* p) {
    uint32_t a;
    asm("{ .reg .u64 t; cvta.to.shared.u64 t, %1; cvt.u32.u64 %0, t; }" : "=r"(a) : "l"(p));
    return a;
}
__device__ __forceinline__ void cp16(uint32_t dst, const void* src) {
    asm volatile("cp.async.cg.shared.global [%0], [%1], 16;" :: "r"(dst), "l"(src));
}
__device__ __forceinline__ void cp_commit() {
    asm volatile("cp.async.commit_group;" ::: "memory");
}
template<int N> __device__ __forceinline__ void cp_wait() {
    asm volatile("cp.async.wait_group %0;" :: "n"(N) : "memory");
}
__device__ __forceinline__ void mma16816(float* c,
    uint32_t a0, uint32_t a1, uint32_t a2, uint32_t a3, uint32_t b0, uint32_t b1) {
    asm volatile(
        "mma.sync.aligned.m16n8k16.row.col.f32.bf16.bf16.f32 "
        "{%0,%1,%2,%3}, {%4,%5,%6,%7}, {%8,%9}, {%0,%1,%2,%3};"
        : "+f"(c[0]), "+f"(c[1]), "+f"(c[2]), "+f"(c[3])
        : "r"(a0), "r"(a1), "r"(a2), "r"(a3), "r"(b0), "r"(b1));
}

// ---------------------------------------------------------------------------
// Mask dtype detector + canonicalizer
// ---------------------------------------------------------------------------
__global__ void detect_mask_kernel(const unsigned char* __restrict__ m, int nbytes) {
    __shared__ int has_big, has_mis;
    if (threadIdx.x == 0) { has_big = 0; has_mis = 0; }
    __syncthreads();
    int lb = 0, lm = 0;
    for (int i = threadIdx.x; i < nbytes; i += blockDim.x) {
        unsigned char b = m[i];
        if (b > 1) lb = 1;
        else if (b != 0 && (i & 3) != 0) lm = 1;
    }
    if (lb) atomicOr(&has_big, 1);
    if (lm) atomicOr(&has_mis, 1);
    __syncthreads();
    if (threadIdx.x == 0)
        g_mask_mode = has_big ? 2 : (has_mis ? 0 : 1);
}

__device__ __forceinline__ bool mask_at(const char* m, long idx, int mode) {
    if (mode == 0) return ((const unsigned char*)m)[idx] != 0;
    if (mode == 1) return ((const int*)m)[idx] != 0;
    return ((const float*)m)[idx] != 0.0f;
}

__global__ __launch_bounds__(256) void mask_canon_kernel(
    const char* __restrict__ m, unsigned char* __restrict__ out, long n)
{
    long i = ((long)blockIdx.x * blockDim.x + threadIdx.x) * 4;
    if (i >= n) return;
    int mode = g_mask_mode;
    uchar4 r;
    r.x = mask_at(m, i + 0, mode) ? 1 : 0;
    r.y = mask_at(m, i + 1, mode) ? 1 : 0;
    r.z = mask_at(m, i + 2, mode) ? 1 : 0;
    r.w = mask_at(m, i + 3, mode) ? 1 : 0;
    *(uchar4*)(out + i) = r;
}

// ---------------------------------------------------------------------------
// fp32 -> bf16 (hi, lo) elementwise split.
// ---------------------------------------------------------------------------
__global__ __launch_bounds__(256) void conv_split_kernel(
    const float* __restrict__ in, __nv_bfloat16* __restrict__ hi,
    __nv_bfloat16* __restrict__ lo, long n)
{
    long i = ((long)blockIdx.x * blockDim.x + threadIdx.x) * 4;
    if (i >= n) return;
    float4 a = *(const float4*)&in[i];
    float av[4] = {a.x, a.y, a.z, a.w};
    ushort4 hv, lv;
    unsigned short* hp = &hv.x; unsigned short* lp = &lv.x;
#pragma unroll
    for (int j = 0; j < 4; j++) {
        __nv_bfloat16 h = __float2bfloat16_rn(av[j]);
        __nv_bfloat16 l = __float2bfloat16_rn(av[j] - __bfloat162float(h));
        hp[j] = *(unsigned short*)&h;
        lp[j] = *(unsigned short*)&l;
    }
    *(ushort4*)&hi[i] = hv;
    *(ushort4*)&lo[i] = lv;
}

// ---------------------------------------------------------------------------
// Weight transpose + split: W[K=1024][N=1024] fp32 -> hiT/loT [N][K] bf16
// ---------------------------------------------------------------------------
__global__ __launch_bounds__(256) void conv_transpose_kernel(
    const float* __restrict__ W, __nv_bfloat16* __restrict__ hiT,
    __nv_bfloat16* __restrict__ loT)
{
    __shared__ float tile[32][33];
    int kb = blockIdx.y * 32, nb = blockIdx.x * 32;
    int tx = threadIdx.x & 31, ty = threadIdx.x >> 5;
#pragma unroll
    for (int r = 0; r < 4; r++) {
        int kk = ty * 4 + r;
        tile[kk][tx] = W[(long)(kb + kk) * EMB + nb + tx];
    }
    __syncthreads();
#pragma unroll
    for (int r = 0; r < 4; r++) {
        int nn = ty * 4 + r;
        float v = tile[tx][nn];
        __nv_bfloat16 h = __float2bfloat16_rn(v);
        __nv_bfloat16 l = __float2bfloat16_rn(v - __bfloat162float(h));
        long o = (long)(nb + nn) * EMB + kb + tx;
        hiT[o] = h;
        loT[o] = l;
    }
}

// ---------------------------------------------------------------------------
// V transpose + split per head: v[b,s,h*64+d] -> vt[(bh)*64+d][s] hi/lo bf16
// ---------------------------------------------------------------------------
__global__ __launch_bounds__(256) void conv_vt_kernel(
    const float* __restrict__ v, __nv_bfloat16* __restrict__ vth,
    __nv_bfloat16* __restrict__ vtl)
{
    __shared__ float tile[32][33];
    int bh = blockIdx.z;
    int b = bh >> 4, h = bh & 15;
    int s0 = blockIdx.x * 32, d0 = blockIdx.y * 32;
    int tx = threadIdx.x & 31, ty = threadIdx.x >> 5;
#pragma unroll
    for (int r = 0; r < 4; r++) {
        int ss = ty * 4 + r;
        tile[ss][tx] = v[((long)(b * SQ + s0 + ss)) * EMB + h * DKK + d0 + tx];
    }
    __syncthreads();
#pragma unroll
    for (int r = 0; r < 4; r++) {
        int dd = ty * 4 + r;
        float val = tile[tx][dd];
        __nv_bfloat16 hh = __float2bfloat16_rn(val);
        __nv_bfloat16 ll = __float2bfloat16_rn(val - __bfloat162float(hh));
        long o = ((long)bh * DKK + d0 + dd) * SQ + s0 + tx;
        vth[o] = hh;
        vtl[o] = ll;
    }
}

// ---------------------------------------------------------------------------
// Split-bf16 HMMA GEMM: C[M][1024] = A[M][1024] * B[1024][1024]
// ---------------------------------------------------------------------------
#define GBK 32
#define GKSTEPS (EMB / GBK)
#define ROWP 40
#define MAT_BYTES (128 * ROWP * 2)
#define OA_H 0
#define OA_L (MAT_BYTES)
#define OB_H (2 * MAT_BYTES)
#define OB_L (3 * MAT_BYTES)
#define STG (4 * MAT_BYTES)
#define GEMM_SMEM (2 * STG)

__global__ __launch_bounds__(256, 1) void gemm_mma_kernel(
    const __nv_bfloat16* __restrict__ Ah, const __nv_bfloat16* __restrict__ Al,
    const __nv_bfloat16* __restrict__ BhT, const __nv_bfloat16* __restrict__ BlT,
    float* __restrict__ C)
{
    extern __shared__ char smem[];
    uint32_t sb = smem_u32(smem);

    const int tid = threadIdx.x;
    const int wid = tid >> 5;
    const int lane = tid & 31;
    const int wm = wid >> 2;
    const int wn = wid & 3;
    const int bm = blockIdx.y * 128;
    const int bn = blockIdx.x * 128;

    const int lr = lane >> 2;
    const int lc = (lane & 3) * 2;

    float acc[4][4][4];
#pragma unroll
    for (int i = 0; i < 4; i++)
#pragma unroll
        for (int j = 0; j < 4; j++)
#pragma unroll
            for (int v = 0; v < 4; v++) acc[i][j][v] = 0.0f;

    auto load_stage = [&](int s, int k0) {
        uint32_t base = sb + s * STG;
#pragma unroll
        for (int c = 0; c < 2; c++) {
            int ch = tid + c * 256;
            int row = ch >> 2, j = ch & 3;
            uint32_t soff = (uint32_t)(row * 80 + j * 16);
            long ga = (long)(bm + row) * EMB + k0 + j * 8;
            long gb = (long)(bn + row) * EMB + k0 + j * 8;
            cp16(base + OA_H + soff, Ah + ga);
            cp16(base + OA_L + soff, Al + ga);
            cp16(base + OB_H + soff, BhT + gb);
            cp16(base + OB_L + soff, BlT + gb);
        }
        cp_commit();
    };

    load_stage(0, 0);

    for (int t = 0; t < GKSTEPS; t++) {
        int s = t & 1;
        if (t + 1 < GKSTEPS) {
            load_stage(s ^ 1, (t + 1) * GBK);
            cp_wait<1>();
        } else {
            cp_wait<0>();
        }
        __syncthreads();

        const char* st = smem + s * STG;
#pragma unroll
        for (int ks = 0; ks < 2; ks++) {
            int kb = ks * 16;
            uint32_t bh[4][2], bl[4][2];
#pragma unroll
            for (int ni = 0; ni < 4; ni++) {
                int n = wn * 32 + ni * 8 + lr;
                int k = kb + lc;
                const char* ph = st + OB_H + (n * ROWP + k) * 2;
                const char* pl = st + OB_L + (n * ROWP + k) * 2;
                bh[ni][0] = *(const uint32_t*)ph;
                bh[ni][1] = *(const uint32_t*)(ph + 16);
                bl[ni][0] = *(const uint32_t*)pl;
                bl[ni][1] = *(const uint32_t*)(pl + 16);
            }
#pragma unroll
            for (int mi = 0; mi < 4; mi++) {
                int m = wm * 64 + mi * 16 + lr;
                int k = kb + lc;
                const char* ph = st + OA_H + (m * ROWP + k) * 2;
                const char* pl = st + OA_L + (m * ROWP + k) * 2;
                uint32_t ah0 = *(const uint32_t*)ph;
                uint32_t ah1 = *(const uint32_t*)(ph + 8 * ROWP * 2);
                uint32_t ah2 = *(const uint32_t*)(ph + 16);
                uint32_t ah3 = *(const uint32_t*)(ph + 8 * ROWP * 2 + 16);
                uint32_t al0 = *(const uint32_t*)pl;
                uint32_t al1 = *(const uint32_t*)(pl + 8 * ROWP * 2);
                uint32_t al2 = *(const uint32_t*)(pl + 16);
                uint32_t al3 = *(const uint32_t*)(pl + 8 * ROWP * 2 + 16);
#pragma unroll
                for (int ni = 0; ni < 4; ni++) {
                    mma16816(acc[mi][ni], ah0, ah1, ah2, ah3, bh[ni][0], bh[ni][1]);
                    mma16816(acc[mi][ni], ah0, ah1, ah2, ah3, bl[ni][0], bl[ni][1]);
                    mma16816(acc[mi][ni], al0, al1, al2, al3, bh[ni][0], bh[ni][1]);
                }
            }
        }
        __syncthreads();
    }

#pragma unroll
    for (int mi = 0; mi < 4; mi++) {
#pragma unroll
        for (int ni = 0; ni < 4; ni++) {
            int r = bm + wm * 64 + mi * 16 + lr;
            int cc = bn + wn * 32 + ni * 8 + lc;
            float2 v0 = {acc[mi][ni][0], acc[mi][ni][1]};
            float2 v1 = {acc[mi][ni][2], acc[mi][ni][3]};
            *(float2*)&C[(long)r * EMB + cc] = v0;
            *(float2*)&C[(long)(r + 8) * EMB + cc] = v1;
        }
    }
}

// ---------------------------------------------------------------------------
// Fused scores + mask + softmax: one CTA per (bh, 16 q-rows).
// S[16][2048] in smem; QK^T via split-bf16 mma; normalized attn written once.
// ---------------------------------------------------------------------------
#define AT_SPITCH 2056                    // fp32 elems per S row (padded)
#define AT_KPITCH 72                      // bf16 elems per K/Q smem row
#define AT_S_OFF 0                        // 16*2056*4 = 131584
#define AT_QH_OFF 131584                  // 16*72*2 = 2304
#define AT_QL_OFF (AT_QH_OFF + 2304)
#define AT_KST_OFF (AT_QL_OFF + 2304)     // 136192
#define AT_KSTG 36864                     // Kh 18432 + Kl 18432
#define AT_RED_OFF (AT_KST_OFF + 2*AT_KSTG)  // 209920
#define AT_INV_OFF (AT_RED_OFF + 1024)
#define ATTN_SMEM (AT_INV_OFF + 128)      // 211072

__global__ __launch_bounds__(256, 1) void attn_fused_kernel(
    const __nv_bfloat16* __restrict__ qh, const __nv_bfloat16* __restrict__ ql,
    const __nv_bfloat16* __restrict__ kh, const __nv_bfloat16* __restrict__ kl,
    const unsigned char* __restrict__ mask8, float* __restrict__ attn)
{
    extern __shared__ char smem[];
    uint32_t sb = smem_u32(smem);
    float* S = (float*)(smem + AT_S_OFF);
    float* red = (float*)(smem + AT_RED_OFF);
    float* invs = (float*)(smem + AT_INV_OFF);

    const int tid = threadIdx.x;
    const int wid = tid >> 5;
    const int lane = tid & 31;
    const int lr = lane >> 2;
    const int lc = (lane & 3) * 2;
    const int bh = blockIdx.y;
    const int b = bh >> 4, h = bh & 15;
    const int q0 = blockIdx.x * 16;

    // Load Q 16x64 hi/lo into smem
    {
        int r = tid >> 4, c = (tid & 15) * 4;
        long g = ((long)(b * SQ + q0 + r)) * EMB + h * DKK + c;
        *(uint2*)(smem + AT_QH_OFF + (r * AT_KPITCH + c) * 2) = *(const uint2*)(qh + g);
        *(uint2*)(smem + AT_QL_OFF + (r * AT_KPITCH + c) * 2) = *(const uint2*)(ql + g);
    }

    auto loadK = [&](int s, int k0) {
        uint32_t base = sb + AT_KST_OFF + s * AT_KSTG;
#pragma unroll
        for (int i = 0; i < 4; i++) {
            int u = tid + 256 * i;              // 1024 16B-units per matrix
            int row = u >> 3, cu = u & 7;
            long g = ((long)(b * SQ + k0 + row)) * EMB + h * DKK + cu * 8;
            cp16(base + row * 144 + cu * 16, kh + g);
            cp16(base + 18432 + row * 144 + cu * 16, kl + g);
        }
        cp_commit();
    };

    loadK(0, 0);
    __syncthreads();   // Q smem visible

    // Q fragments (registers, reused for all k-tiles)
    uint32_t qhf[4][4], qlf[4][4];
#pragma unroll
    for (int ks = 0; ks < 4; ks++) {
        int o = (lr * AT_KPITCH + ks * 16 + lc) * 2;
        qhf[ks][0] = *(uint32_t*)(smem + AT_QH_OFF + o);
        qhf[ks][1] = *(uint32_t*)(smem + AT_QH_OFF + o + 8 * AT_KPITCH * 2);
        qhf[ks][2] = *(uint32_t*)(smem + AT_QH_OFF + o + 16);
        qhf[ks][3] = *(uint32_t*)(smem + AT_QH_OFF + o + 8 * AT_KPITCH * 2 + 16);
        qlf[ks][0] = *(uint32_t*)(smem + AT_QL_OFF + o);
        qlf[ks][1] = *(uint32_t*)(smem + AT_QL_OFF + o + 8 * AT_KPITCH * 2);
        qlf[ks][2] = *(uint32_t*)(smem + AT_QL_OFF + o + 16);
        qlf[ks][3] = *(uint32_t*)(smem + AT_QL_OFF + o + 8 * AT_KPITCH * 2 + 16);
    }

    // Scores: 16 k-tiles of 128 columns
    for (int kt = 0; kt < 16; kt++) {
        int s = kt & 1;
        if (kt + 1 < 16) { loadK(s ^ 1, (kt + 1) * 128); cp_wait<1>(); }
        else             { cp_wait<0>(); }
        __syncthreads();

        const char* Kh = smem + AT_KST_OFF + s * AT_KSTG;
        const char* Kl = Kh + 18432;

        float acc[2][4];
#pragma unroll
        for (int ni = 0; ni < 2; ni++)
#pragma unroll
            for (int v = 0; v < 4; v++) acc[ni][v] = 0.0f;

#pragma unroll
        for (int ks = 0; ks < 4; ks++) {
#pragma unroll
            for (int ni = 0; ni < 2; ni++) {
                int n = wid * 16 + ni * 8 + lr;
                int o = (n * AT_KPITCH + ks * 16 + lc) * 2;
                uint32_t b0h = *(const uint32_t*)(Kh + o);
                uint32_t b1h = *(const uint32_t*)(Kh + o + 16);
                uint32_t b0l = *(const uint32_t*)(Kl + o);
                uint32_t b1l = *(const uint32_t*)(Kl + o + 16);
                mma16816(acc[ni], qhf[ks][0], qhf[ks][1], qhf[ks][2], qhf[ks][3], b0h, b1h);
                mma16816(acc[ni], qhf[ks][0], qhf[ks][1], qhf[ks][2], qhf[ks][3], b0l, b1l);
                mma16816(acc[ni], qlf[ks][0], qlf[ks][1], qlf[ks][2], qlf[ks][3], b0h, b1h);
            }
        }

#pragma unroll
        for (int ni = 0; ni < 2; ni++) {
            int col = kt * 128 + wid * 16 + ni * 8 + lc;
            float2 v0 = {acc[ni][0] * 0.125f, acc[ni][1] * 0.125f};
            float2 v1 = {acc[ni][2] * 0.125f, acc[ni][3] * 0.125f};
            *(float2*)&S[lr * AT_SPITCH + col] = v0;
            *(float2*)&S[(lr + 8) * AT_SPITCH + col] = v1;
        }
        __syncthreads();   // all reads/writes of this tile done before next stage reuse
    }

    // Softmax over each of the 16 rows (2048 elems)
    const int r = tid >> 4, seg = tid & 15;
    const long mrow = ((long)b * SQ + q0 + r) * SQ;

    // pass 1: apply mask, find max
    float mx = -3.4e38f;
#pragma unroll 4
    for (int j = 0; j < 32; j++) {
        int c = seg * 4 + j * 64;
        float4 s4 = *(float4*)&S[r * AT_SPITCH + c];
        uchar4 m4 = *(const uchar4*)(mask8 + mrow + c);
        if (m4.x) s4.x = -1e9f;
        if (m4.y) s4.y = -1e9f;
        if (m4.z) s4.z = -1e9f;
        if (m4.w) s4.w = -1e9f;
        *(float4*)&S[r * AT_SPITCH + c] = s4;
        mx = fmaxf(mx, fmaxf(fmaxf(s4.x, s4.y), fmaxf(s4.z, s4.w)));
    }
    red[r * 16 + seg] = mx;
    __syncthreads();
    float bm = -3.4e38f;
#pragma unroll
    for (int i = 0; i < 16; i++) bm = fmaxf(bm, red[r * 16 + i]);
    __syncthreads();

    // pass 2: exp + partial sum
    float ps = 0.0f;
#pragma unroll 4
    for (int j = 0; j < 32; j++) {
        int c = seg * 4 + j * 64;
        float4 s4 = *(float4*)&S[r * AT_SPITCH + c];
        s4.x = __expf(s4.x - bm); s4.y = __expf(s4.y - bm);
        s4.z = __expf(s4.z - bm); s4.w = __expf(s4.w - bm);
        ps += (s4.x + s4.y) + (s4.z + s4.w);
        *(float4*)&S[r * AT_SPITCH + c] = s4;
    }
    red[r * 16 + seg] = ps;
    __syncthreads();
    float sum = 0.0f;
#pragma unroll
    for (int i = 0; i < 16; i++) sum += red[r * 16 + i];
    if (seg == 0) invs[r] = 1.0f / sum;
    __syncthreads();

    // pass 3: scale + coalesced write
    float* orow = attn + ((long)bh * SQ + q0) * SQ;
#pragma unroll 4
    for (int i = 0; i < 32; i++) {
        int u = tid + 256 * i;              // float4 unit, 8192 total
        int row = u >> 9;
        int cu = u & 511;
        float4 e4 = *(float4*)&S[row * AT_SPITCH + cu * 4];
        float inv = invs[row];
        e4.x *= inv; e4.y *= inv; e4.z *= inv; e4.w *= inv;
        *(float4*)(orow + (long)u * 4) = e4;
    }
}

// ---------------------------------------------------------------------------
// PV via mma: ph[b,q,h*64+d] = sum_k attn[bh,q,k] * v[b,k,h*64+d]
// attn fp32 tiles converted to bf16 hi/lo in smem; V pre-transposed per head.
// ---------------------------------------------------------------------------
#define PV_PF_OFF 0                        // 2 x 32768 fp32 P stages
#define PV_PH_OFF 65536                    // 128*72*2 = 18432
#define PV_PL_OFF (PV_PH_OFF + 18432)
#define PV_VT_OFF (PV_PL_OFF + 18432)      // 2 stages x (Vth 9216 + Vtl 9216)
#define PV_VSTG 18432
#define PV_SMEM (PV_VT_OFF + 2*PV_VSTG)    // 139264

__global__ __launch_bounds__(256, 1) void pv_mma_kernel(
    const float* __restrict__ attn,
    const __nv_bfloat16* __restrict__ vth, const __nv_bfloat16* __restrict__ vtl,
    float* __restrict__ ph)
{
    extern __shared__ char smem[];
    uint32_t sb = smem_u32(smem);

    const int tid = threadIdx.x;
    const int wid = tid >> 5;
    const int lane = tid & 31;
    const int lr = lane >> 2;
    const int lc = (lane & 3) * 2;
    const int bh = blockIdx.y;
    const int b = bh >> 4, h = bh & 15;
    const int m0 = blockIdx.x * 128;

    auto loadT = [&](int s, int k0) {
        uint32_t pb = sb + PV_PF_OFF + s * 32768;
#pragma unroll
        for (int i = 0; i < 8; i++) {
            int u = tid + 256 * i;              // 2048 16B-units
            int row = u >> 4, cu = u & 15;
            cp16(pb + u * 16, attn + ((long)bh * SQ + m0 + row) * SQ + k0 + cu * 4);
        }
        uint32_t vb = sb + PV_VT_OFF + s * PV_VSTG;
#pragma unroll
        for (int i = 0; i < 2; i++) {
            int u = tid + 256 * i;              // 512 units per matrix
            int d = u >> 3, cu = u & 7;
            long g = ((long)bh * DKK + d) * SQ + k0 + cu * 8;
            cp16(vb + d * 144 + cu * 16, vth + g);
            cp16(vb + 9216 + d * 144 + cu * 16, vtl + g);
        }
        cp_commit();
    };

    float acc[8][4];
#pragma unroll
    for (int i = 0; i < 8; i++)
#pragma unroll
        for (int v = 0; v < 4; v++) acc[i][v] = 0.0f;

    loadT(0, 0);

    for (int kt = 0; kt < 32; kt++) {
        int s = kt & 1;
        if (kt + 1 < 32) { loadT(s ^ 1, (kt + 1) * 64); cp_wait<1>(); }
        else             { cp_wait<0>(); }
        __syncthreads();

        // Convert P fp32 -> bf16 hi/lo smem (each element exactly once)
        const float* Pf = (const float*)(smem + PV_PF_OFF + s * 32768);
#pragma unroll
        for (int i = 0; i < 8; i++) {
            int u = tid + 256 * i;              // float4 unit, 2048 total
            float4 p = *(const float4*)(Pf + (long)u * 4);
            int row = u >> 4, col = (u & 15) * 4;
            float pv[4] = {p.x, p.y, p.z, p.w};
            unsigned short hh[4], ll[4];
#pragma unroll
            for (int j = 0; j < 4; j++) {
                __nv_bfloat16 hb = __float2bfloat16_rn(pv[j]);
                __nv_bfloat16 lb = __float2bfloat16_rn(pv[j] - __bfloat162float(hb));
                hh[j] = *(unsigned short*)&hb;
                ll[j] = *(unsigned short*)&lb;
            }
            *(uint2*)(smem + PV_PH_OFF + (row * 72 + col) * 2) = *(uint2*)hh;
            *(uint2*)(smem + PV_PL_OFF + (row * 72 + col) * 2) = *(uint2*)ll;
        }
        __syncthreads();

        const char* Ph = smem + PV_PH_OFF;
        const char* Pl = smem + PV_PL_OFF;
        const char* Vh = smem + PV_VT_OFF + s * PV_VSTG;
        const char* Vl = Vh + 9216;

#pragma unroll
        for (int ks = 0; ks < 4; ks++) {
            int ao = ((wid * 16 + lr) * 72 + ks * 16 + lc) * 2;
            uint32_t ah0 = *(const uint32_t*)(Ph + ao);
            uint32_t ah1 = *(const uint32_t*)(Ph + ao + 8 * 144);
            uint32_t ah2 = *(const uint32_t*)(Ph + ao + 16);
            uint32_t ah3 = *(const uint32_t*)(Ph + ao + 8 * 144 + 16);
            uint32_t al0 = *(const uint32_t*)(Pl + ao);
            uint32_t al1 = *(const uint32_t*)(Pl + ao + 8 * 144);
            uint32_t al2 = *(const uint32_t*)(Pl + ao + 16);
            uint32_t al3 = *(const uint32_t*)(Pl + ao + 8 * 144 + 16);
#pragma unroll
            for (int nt = 0; nt < 8; nt++) {
                int bo = ((nt * 8 + lr) * 72 + ks * 16 + lc) * 2;
                uint32_t b0h = *(const uint32_t*)(Vh + bo);
                uint32_t b1h = *(const uint32_t*)(Vh + bo + 16);
                uint32_t b0l = *(const uint32_t*)(Vl + bo);
                uint32_t b1l = *(const uint32_t*)(Vl + bo + 16);
                mma16816(acc[nt], ah0, ah1, ah2, ah3, b0h, b1h);
                mma16816(acc[nt], ah0, ah1, ah2, ah3, b0l, b1l);
                mma16816(acc[nt], al0, al1, al2, al3, b0h, b1h);
            }
        }
        __syncthreads();   // mma reads done before next cvt overwrites Ph/Pl
    }

#pragma unroll
    for (int nt = 0; nt < 8; nt++) {
        int row = m0 + wid * 16 + lr;
        int d = nt * 8 + lc;
        long o = ((long)(b * SQ + row)) * EMB + h * DKK + d;
        float2 v0 = {acc[nt][0], acc[nt][1]};
        float2 v1 = {acc[nt][2], acc[nt][3]};
        *(float2*)&ph[o] = v0;
        *(float2*)&ph[o + 8L * EMB] = v1;
    }
}

// ---------------------------------------------------------------------------
extern "C" void kernel_launch(void* const* d_in, const int* in_sizes, int n_in,
                              void* d_out, int out_size)
{
    const float* Q   = (const float*)d_in[0];
    const float* K   = (const float*)d_in[1];
    const float* V   = (const float*)d_in[2];
    const char*  msk = (const char*)d_in[3];
    const float* WQ  = (const float*)d_in[4];
    const float* WK  = (const float*)d_in[5];
    const float* WV  = (const float*)d_in[6];
    const float* Wfc = (const float*)d_in[7];
    float* out = (float*)d_out;

    float *pq, *pk, *pv, *pph, *pfb;
    __nv_bfloat16 *pah, *pal, *pbh, *pbl;
    __nv_bfloat16 *pqh, *pql, *pkh, *pkl, *pvth, *pvtl;
    unsigned char* pm8;
    cudaGetSymbolAddress((void**)&pq,  g_q);
    cudaGetSymbolAddress((void**)&pk,  g_k);
    cudaGetSymbolAddress((void**)&pv,  g_v);
    cudaGetSymbolAddress((void**)&pph, g_ph);
    cudaGetSymbolAddress((void**)&pfb, g_attn_fb);
    cudaGetSymbolAddress((void**)&pah, g_ah);
    cudaGetSymbolAddress((void**)&pal, g_al);
    cudaGetSymbolAddress((void**)&pbh, g_bhT);
    cudaGetSymbolAddress((void**)&pbl, g_blT);
    cudaGetSymbolAddress((void**)&pqh, g_qh);
    cudaGetSymbolAddress((void**)&pql, g_ql);
    cudaGetSymbolAddress((void**)&pkh, g_kh);
    cudaGetSymbolAddress((void**)&pkl, g_kl);
    cudaGetSymbolAddress((void**)&pvth, g_vth);
    cudaGetSymbolAddress((void**)&pvtl, g_vtl);
    cudaGetSymbolAddress((void**)&pm8, g_mask8);

    float* attnbuf = ((long)out_size >= PRED_ELEMS + ATTN_ELEMS)
                         ? (out + PRED_ELEMS) : pfb;

    cudaFuncSetAttribute(gemm_mma_kernel,
                         cudaFuncAttributeMaxDynamicSharedMemorySize, GEMM_SMEM);
    cudaFuncSetAttribute(attn_fused_kernel,
                         cudaFuncAttributeMaxDynamicSharedMemorySize, ATTN_SMEM);
    cudaFuncSetAttribute(pv_mma_kernel,
                         cudaFuncAttributeMaxDynamicSharedMemorySize, PV_SMEM);

    detect_mask_kernel<<<1, 256>>>((const unsigned char*)msk, 65536);
    mask_canon_kernel<<<(unsigned)((MASK_ELEMS / 4 + 255) / 256), 256>>>(msk, pm8, MASK_ELEMS);

    const long AN = (long)BS * EMB;
    dim3 cg((unsigned)((AN / 4 + 255) / 256));
    dim3 tg(EMB / 32, EMB / 32);
    dim3 gg(EMB / 128, BS / 128);

    // Projections
    conv_split_kernel<<<cg, 256>>>(Q, pah, pal, AN);
    conv_transpose_kernel<<<tg, 256>>>(WQ, pbh, pbl);
    gemm_mma_kernel<<<gg, 256, GEMM_SMEM>>>(pah, pal, pbh, pbl, pq);

    conv_split_kernel<<<cg, 256>>>(K, pah, pal, AN);
    conv_transpose_kernel<<<tg, 256>>>(WK, pbh, pbl);
    gemm_mma_kernel<<<gg, 256, GEMM_SMEM>>>(pah, pal, pbh, pbl, pk);

    conv_split_kernel<<<cg, 256>>>(V, pah, pal, AN);
    conv_transpose_kernel<<<tg, 256>>>(WV, pbh, pbl);
    gemm_mma_kernel<<<gg, 256, GEMM_SMEM>>>(pah, pal, pbh, pbl, pv);

    // Attention-side conversions
    conv_split_kernel<<<cg, 256>>>(pq, pqh, pql, AN);
    conv_split_kernel<<<cg, 256>>>(pk, pkh, pkl, AN);
    conv_vt_kernel<<<dim3(SQ / 32, DKK / 32, BH), 256>>>(pv, pvth, pvtl);

    // Fused scores + mask + softmax -> attn
    attn_fused_kernel<<<dim3(SQ / 16, BH), 256, ATTN_SMEM>>>(
        pqh, pql, pkh, pkl, pm8, attnbuf);

    // PV
    pv_mma_kernel<<<dim3(SQ / 128, BH), 256, PV_SMEM>>>(attnbuf, pvth, pvtl, pph);

    // Output projection
    conv_split_kernel<<<cg, 256>>>(pph, pah, pal, AN);
    conv_transpose_kernel<<<tg, 256>>>(Wfc, pbh, pbl);
    gemm_mma_kernel<<<gg, 256, GEMM_SMEM>>>(pah, pal, pbh, pbl, out);
}

// round 6
// speedup vs baseline: 1.7606x; 1.0030x over previous
#include <cuda_runtime.h>
#include <cuda_bf16.h>
#include <cstdint>

// Problem constants (fixed by reference)
#define BQ 4
#define SQ 2048
#define EMB 1024
#define NHH 16
#define DKK 64
#define BS (BQ*SQ)            // 8192 rows
#define BH (BQ*NHH)           // 64 (b,h) pairs
#define PRED_ELEMS (8388608L)          // BS*EMB
#define ATTN_ELEMS (268435456L)        // BH*SQ*SQ
#define MASK_ELEMS (16777216L)         // BQ*SQ*SQ

// Scratch (device globals: sanctioned, no cudaMalloc)
__device__ float g_v[BS*EMB];
__device__ float g_attn_fb[ATTN_ELEMS];   // fallback if attn not part of d_out
__device__ int   g_mask_mode;             // 0=u8, 1=i32, 2=f32

// bf16 split buffers
__device__ __nv_bfloat16 g_ah[BS*EMB];    // GEMM A hi   [M][K]
__device__ __nv_bfloat16 g_al[BS*EMB];    // GEMM A lo
__device__ __nv_bfloat16 g_bhT[EMB*EMB];  // GEMM B hi, transposed [N][K]
__device__ __nv_bfloat16 g_blT[EMB*EMB];  // GEMM B lo
__device__ __nv_bfloat16 g_qh[BS*EMB];    // q hi/lo [b,s,emb]
__device__ __nv_bfloat16 g_ql[BS*EMB];
__device__ __nv_bfloat16 g_kh[BS*EMB];    // k hi/lo
__device__ __nv_bfloat16 g_kl[BS*EMB];
__device__ __nv_bfloat16 g_vth[BH*DKK*SQ]; // v hi/lo transposed per head
__device__ __nv_bfloat16 g_vtl[BH*DKK*SQ];
__device__ unsigned char g_mask8[MASK_ELEMS];  // canonical u8 mask

// ---------------------------------------------------------------------------
// Helpers
// ---------------------------------------------------------------------------
__device__ __forceinline__ uint32_t smem_u32(const void* p) {
    uint32_t a;
    asm("{ .reg .u64 t; cvta.to.shared.u64 t, %1; cvt.u32.u64 %0, t; }" : "=r"(a) : "l"(p));
    return a;
}
__device__ __forceinline__ void cp16(uint32_t dst, const void* src) {
    asm volatile("cp.async.cg.shared.global [%0], [%1], 16;" :: "r"(dst), "l"(src));
}
__device__ __forceinline__ void cp_commit() {
    asm volatile("cp.async.commit_group;" ::: "memory");
}
template<int N> __device__ __forceinline__ void cp_wait() {
    asm volatile("cp.async.wait_group %0;" :: "n"(N) : "memory");
}
__device__ __forceinline__ void mma16816(float* c,
    uint32_t a0, uint32_t a1, uint32_t a2, uint32_t a3, uint32_t b0, uint32_t b1) {
    asm volatile(
        "mma.sync.aligned.m16n8k16.row.col.f32.bf16.bf16.f32 "
        "{%0,%1,%2,%3}, {%4,%5,%6,%7}, {%8,%9}, {%0,%1,%2,%3};"
        : "+f"(c[0]), "+f"(c[1]), "+f"(c[2]), "+f"(c[3])
        : "r"(a0), "r"(a1), "r"(a2), "r"(a3), "r"(b0), "r"(b1));
}
__device__ __forceinline__ void ldmx4(uint32_t& r0, uint32_t& r1, uint32_t& r2, uint32_t& r3,
                                      uint32_t addr) {
    asm volatile("ldmatrix.sync.aligned.m8n8.x4.shared.b16 {%0,%1,%2,%3}, [%4];"
                 : "=r"(r0), "=r"(r1), "=r"(r2), "=r"(r3) : "r"(addr));
}
__device__ __forceinline__ void split_bf16(float v, unsigned short& h, unsigned short& l) {
    __nv_bfloat16 hb = __float2bfloat16_rn(v);
    __nv_bfloat16 lb = __float2bfloat16_rn(v - __bfloat162float(hb));
    h = *(unsigned short*)&hb;
    l = *(unsigned short*)&lb;
}

// ---------------------------------------------------------------------------
// Mask dtype detector + canonicalizer
// ---------------------------------------------------------------------------
__global__ void detect_mask_kernel(const unsigned char* __restrict__ m, int nbytes) {
    __shared__ int has_big, has_mis;
    if (threadIdx.x == 0) { has_big = 0; has_mis = 0; }
    __syncthreads();
    int lb = 0, lm = 0;
    for (int i = threadIdx.x; i < nbytes; i += blockDim.x) {
        unsigned char b = m[i];
        if (b > 1) lb = 1;
        else if (b != 0 && (i & 3) != 0) lm = 1;
    }
    if (lb) atomicOr(&has_big, 1);
    if (lm) atomicOr(&has_mis, 1);
    __syncthreads();
    if (threadIdx.x == 0)
        g_mask_mode = has_big ? 2 : (has_mis ? 0 : 1);
}

__device__ __forceinline__ bool mask_at(const char* m, long idx, int mode) {
    if (mode == 0) return ((const unsigned char*)m)[idx] != 0;
    if (mode == 1) return ((const int*)m)[idx] != 0;
    return ((const float*)m)[idx] != 0.0f;
}

__global__ __launch_bounds__(256) void mask_canon_kernel(
    const char* __restrict__ m, unsigned char* __restrict__ out, long n)
{
    long i = ((long)blockIdx.x * blockDim.x + threadIdx.x) * 4;
    if (i >= n) return;
    int mode = g_mask_mode;
    uchar4 r;
    r.x = mask_at(m, i + 0, mode) ? 1 : 0;
    r.y = mask_at(m, i + 1, mode) ? 1 : 0;
    r.z = mask_at(m, i + 2, mode) ? 1 : 0;
    r.w = mask_at(m, i + 3, mode) ? 1 : 0;
    *(uchar4*)(out + i) = r;
}

// ---------------------------------------------------------------------------
// fp32 -> bf16 (hi, lo) elementwise split.
// ---------------------------------------------------------------------------
__global__ __launch_bounds__(256) void conv_split_kernel(
    const float* __restrict__ in, __nv_bfloat16* __restrict__ hi,
    __nv_bfloat16* __restrict__ lo, long n)
{
    long i = ((long)blockIdx.x * blockDim.x + threadIdx.x) * 4;
    if (i >= n) return;
    float4 a = *(const float4*)&in[i];
    float av[4] = {a.x, a.y, a.z, a.w};
    ushort4 hv, lv;
    unsigned short* hp = &hv.x; unsigned short* lp = &lv.x;
#pragma unroll
    for (int j = 0; j < 4; j++) split_bf16(av[j], hp[j], lp[j]);
    *(ushort4*)&hi[i] = hv;
    *(ushort4*)&lo[i] = lv;
}

// ---------------------------------------------------------------------------
// Weight transpose + split: W[K=1024][N=1024] fp32 -> hiT/loT [N][K] bf16
// ---------------------------------------------------------------------------
__global__ __launch_bounds__(256) void conv_transpose_kernel(
    const float* __restrict__ W, __nv_bfloat16* __restrict__ hiT,
    __nv_bfloat16* __restrict__ loT)
{
    __shared__ float tile[32][33];
    int kb = blockIdx.y * 32, nb = blockIdx.x * 32;
    int tx = threadIdx.x & 31, ty = threadIdx.x >> 5;
#pragma unroll
    for (int r = 0; r < 4; r++) {
        int kk = ty * 4 + r;
        tile[kk][tx] = W[(long)(kb + kk) * EMB + nb + tx];
    }
    __syncthreads();
#pragma unroll
    for (int r = 0; r < 4; r++) {
        int nn = ty * 4 + r;
        float v = tile[tx][nn];
        unsigned short h, l;
        split_bf16(v, h, l);
        long o = (long)(nb + nn) * EMB + kb + tx;
        *(unsigned short*)&hiT[o] = h;
        *(unsigned short*)&loT[o] = l;
    }
}

// ---------------------------------------------------------------------------
// V transpose + split per head: v[b,s,h*64+d] -> vt[(bh)*64+d][s] hi/lo bf16
// ---------------------------------------------------------------------------
__global__ __launch_bounds__(256) void conv_vt_kernel(
    const float* __restrict__ v, __nv_bfloat16* __restrict__ vth,
    __nv_bfloat16* __restrict__ vtl)
{
    __shared__ float tile[32][33];
    int bh = blockIdx.z;
    int b = bh >> 4, h = bh & 15;
    int s0 = blockIdx.x * 32, d0 = blockIdx.y * 32;
    int tx = threadIdx.x & 31, ty = threadIdx.x >> 5;
#pragma unroll
    for (int r = 0; r < 4; r++) {
        int ss = ty * 4 + r;
        tile[ss][tx] = v[((long)(b * SQ + s0 + ss)) * EMB + h * DKK + d0 + tx];
    }
    __syncthreads();
#pragma unroll
    for (int r = 0; r < 4; r++) {
        int dd = ty * 4 + r;
        float val = tile[tx][dd];
        unsigned short hh, ll;
        split_bf16(val, hh, ll);
        long o = ((long)bh * DKK + d0 + dd) * SQ + s0 + tx;
        *(unsigned short*)&vth[o] = hh;
        *(unsigned short*)&vtl[o] = ll;
    }
}

// ---------------------------------------------------------------------------
// Split-bf16 HMMA GEMM with ldmatrix fragment loads.
// Epilogue: fp32 (Cf) or split bf16 hi/lo (Chi/Clo) per launch args.
// ---------------------------------------------------------------------------
#define GBK 32
#define GKSTEPS (EMB / GBK)
#define ROWP 40
#define MAT_BYTES (128 * ROWP * 2)
#define OA_H 0
#define OA_L (MAT_BYTES)
#define OB_H (2 * MAT_BYTES)
#define OB_L (3 * MAT_BYTES)
#define STG (4 * MAT_BYTES)
#define GEMM_SMEM (2 * STG)

__global__ __launch_bounds__(256, 1) void gemm_mma_kernel(
    const __nv_bfloat16* __restrict__ Ah, const __nv_bfloat16* __restrict__ Al,
    const __nv_bfloat16* __restrict__ BhT, const __nv_bfloat16* __restrict__ BlT,
    float* __restrict__ Cf, __nv_bfloat16* __restrict__ Chi, __nv_bfloat16* __restrict__ Clo)
{
    extern __shared__ char smem[];
    uint32_t sb = smem_u32(smem);

    const int tid = threadIdx.x;
    const int wid = tid >> 5;
    const int lane = tid & 31;
    const int wm = wid >> 2;
    const int wn = wid & 3;
    const int bm = blockIdx.y * 128;
    const int bn = blockIdx.x * 128;

    const int lr = lane >> 2;
    const int lc = (lane & 3) * 2;

    // ldmatrix per-lane offsets (bytes within a matrix block)
    const int lrow = (lane & 7) + ((lane >> 3) & 1) * 8;
    const int lcolb = ((lane >> 4) * 8) * 2;
    uint32_t aoff[4], boff[2];
#pragma unroll
    for (int mi = 0; mi < 4; mi++)
        aoff[mi] = (uint32_t)((wm * 64 + mi * 16 + lrow) * ROWP * 2 + lcolb);
#pragma unroll
    for (int p = 0; p < 2; p++)
        boff[p] = (uint32_t)((wn * 32 + p * 16 + lrow) * ROWP * 2 + lcolb);

    float acc[4][4][4];
#pragma unroll
    for (int i = 0; i < 4; i++)
#pragma unroll
        for (int j = 0; j < 4; j++)
#pragma unroll
            for (int v = 0; v < 4; v++) acc[i][j][v] = 0.0f;

    auto load_stage = [&](int s, int k0) {
        uint32_t base = sb + s * STG;
#pragma unroll
        for (int c = 0; c < 2; c++) {
            int ch = tid + c * 256;
            int row = ch >> 2, j = ch & 3;
            uint32_t soff = (uint32_t)(row * 80 + j * 16);
            long ga = (long)(bm + row) * EMB + k0 + j * 8;
            long gb = (long)(bn + row) * EMB + k0 + j * 8;
            cp16(base + OA_H + soff, Ah + ga);
            cp16(base + OA_L + soff, Al + ga);
            cp16(base + OB_H + soff, BhT + gb);
            cp16(base + OB_L + soff, BlT + gb);
        }
        cp_commit();
    };

    load_stage(0, 0);

    for (int t = 0; t < GKSTEPS; t++) {
        int s = t & 1;
        if (t + 1 < GKSTEPS) {
            load_stage(s ^ 1, (t + 1) * GBK);
            cp_wait<1>();
        } else {
            cp_wait<0>();
        }
        __syncthreads();

        uint32_t stb = sb + s * STG;
#pragma unroll
        for (int ks = 0; ks < 2; ks++) {
            uint32_t kbb = (uint32_t)(ks * 32);   // 16 elems * 2B
            uint32_t bh[4][2], bl[4][2];
#pragma unroll
            for (int p = 0; p < 2; p++) {
                uint32_t r0, r1, r2, r3;
                ldmx4(r0, r1, r2, r3, stb + OB_H + boff[p] + kbb);
                bh[2*p][0] = r0; bh[2*p+1][0] = r1; bh[2*p][1] = r2; bh[2*p+1][1] = r3;
                ldmx4(r0, r1, r2, r3, stb + OB_L + boff[p] + kbb);
                bl[2*p][0] = r0; bl[2*p+1][0] = r1; bl[2*p][1] = r2; bl[2*p+1][1] = r3;
            }
#pragma unroll
            for (int mi = 0; mi < 4; mi++) {
                uint32_t ah0, ah1, ah2, ah3, al0, al1, al2, al3;
                ldmx4(ah0, ah1, ah2, ah3, stb + OA_H + aoff[mi] + kbb);
                ldmx4(al0, al1, al2, al3, stb + OA_L + aoff[mi] + kbb);
#pragma unroll
                for (int ni = 0; ni < 4; ni++) {
                    mma16816(acc[mi][ni], ah0, ah1, ah2, ah3, bh[ni][0], bh[ni][1]);
                    mma16816(acc[mi][ni], ah0, ah1, ah2, ah3, bl[ni][0], bl[ni][1]);
                    mma16816(acc[mi][ni], al0, al1, al2, al3, bh[ni][0], bh[ni][1]);
                }
            }
        }
        __syncthreads();
    }

    if (Chi) {
#pragma unroll
        for (int mi = 0; mi < 4; mi++) {
#pragma unroll
            for (int ni = 0; ni < 4; ni++) {
                int r = bm + wm * 64 + mi * 16 + lr;
                int cc = bn + wn * 32 + ni * 8 + lc;
                ushort2 h0, l0, h1, l1;
                split_bf16(acc[mi][ni][0], h0.x, l0.x);
                split_bf16(acc[mi][ni][1], h0.y, l0.y);
                split_bf16(acc[mi][ni][2], h1.x, l1.x);
                split_bf16(acc[mi][ni][3], h1.y, l1.y);
                long o0 = (long)r * EMB + cc;
                long o1 = (long)(r + 8) * EMB + cc;
                *(ushort2*)&Chi[o0] = h0; *(ushort2*)&Clo[o0] = l0;
                *(ushort2*)&Chi[o1] = h1; *(ushort2*)&Clo[o1] = l1;
            }
        }
    } else {
#pragma unroll
        for (int mi = 0; mi < 4; mi++) {
#pragma unroll
            for (int ni = 0; ni < 4; ni++) {
                int r = bm + wm * 64 + mi * 16 + lr;
                int cc = bn + wn * 32 + ni * 8 + lc;
                float2 v0 = {acc[mi][ni][0], acc[mi][ni][1]};
                float2 v1 = {acc[mi][ni][2], acc[mi][ni][3]};
                *(float2*)&Cf[(long)r * EMB + cc] = v0;
                *(float2*)&Cf[(long)(r + 8) * EMB + cc] = v1;
            }
        }
    }
}

// ---------------------------------------------------------------------------
// Fused scores + mask + softmax: one CTA per (bh, 16 q-rows).
// ---------------------------------------------------------------------------
#define AT_SPITCH 2056
#define AT_KPITCH 72
#define AT_S_OFF 0
#define AT_QH_OFF 131584
#define AT_QL_OFF (AT_QH_OFF + 2304)
#define AT_KST_OFF (AT_QL_OFF + 2304)
#define AT_KSTG 36864
#define AT_RED_OFF (AT_KST_OFF + 2*AT_KSTG)
#define AT_INV_OFF (AT_RED_OFF + 1024)
#define ATTN_SMEM (AT_INV_OFF + 128)

__global__ __launch_bounds__(256, 1) void attn_fused_kernel(
    const __nv_bfloat16* __restrict__ qh, const __nv_bfloat16* __restrict__ ql,
    const __nv_bfloat16* __restrict__ kh, const __nv_bfloat16* __restrict__ kl,
    const unsigned char* __restrict__ mask8, float* __restrict__ attn)
{
    extern __shared__ char smem[];
    uint32_t sb = smem_u32(smem);
    float* S = (float*)(smem + AT_S_OFF);
    float* red = (float*)(smem + AT_RED_OFF);
    float* invs = (float*)(smem + AT_INV_OFF);

    const int tid = threadIdx.x;
    const int wid = tid >> 5;
    const int lane = tid & 31;
    const int lr = lane >> 2;
    const int lc = (lane & 3) * 2;
    const int bh = blockIdx.y;
    const int b = bh >> 4, h = bh & 15;
    const int q0 = blockIdx.x * 16;

    {
        int r = tid >> 4, c = (tid & 15) * 4;
        long g = ((long)(b * SQ + q0 + r)) * EMB + h * DKK + c;
        *(uint2*)(smem + AT_QH_OFF + (r * AT_KPITCH + c) * 2) = *(const uint2*)(qh + g);
        *(uint2*)(smem + AT_QL_OFF + (r * AT_KPITCH + c) * 2) = *(const uint2*)(ql + g);
    }

    auto loadK = [&](int s, int k0) {
        uint32_t base = sb + AT_KST_OFF + s * AT_KSTG;
#pragma unroll
        for (int i = 0; i < 4; i++) {
            int u = tid + 256 * i;
            int row = u >> 3, cu = u & 7;
            long g = ((long)(b * SQ + k0 + row)) * EMB + h * DKK + cu * 8;
            cp16(base + row * 144 + cu * 16, kh + g);
            cp16(base + 18432 + row * 144 + cu * 16, kl + g);
        }
        cp_commit();
    };

    loadK(0, 0);
    __syncthreads();

    uint32_t qhf[4][4], qlf[4][4];
#pragma unroll
    for (int ks = 0; ks < 4; ks++) {
        int o = (lr * AT_KPITCH + ks * 16 + lc) * 2;
        qhf[ks][0] = *(uint32_t*)(smem + AT_QH_OFF + o);
        qhf[ks][1] = *(uint32_t*)(smem + AT_QH_OFF + o + 8 * AT_KPITCH * 2);
        qhf[ks][2] = *(uint32_t*)(smem + AT_QH_OFF + o + 16);
        qhf[ks][3] = *(uint32_t*)(smem + AT_QH_OFF + o + 8 * AT_KPITCH * 2 + 16);
        qlf[ks][0] = *(uint32_t*)(smem + AT_QL_OFF + o);
        qlf[ks][1] = *(uint32_t*)(smem + AT_QL_OFF + o + 8 * AT_KPITCH * 2);
        qlf[ks][2] = *(uint32_t*)(smem + AT_QL_OFF + o + 16);
        qlf[ks][3] = *(uint32_t*)(smem + AT_QL_OFF + o + 8 * AT_KPITCH * 2 + 16);
    }

    for (int kt = 0; kt < 16; kt++) {
        int s = kt & 1;
        if (kt + 1 < 16) { loadK(s ^ 1, (kt + 1) * 128); cp_wait<1>(); }
        else             { cp_wait<0>(); }
        __syncthreads();

        const char* Kh = smem + AT_KST_OFF + s * AT_KSTG;
        const char* Kl = Kh + 18432;

        float acc[2][4];
#pragma unroll
        for (int ni = 0; ni < 2; ni++)
#pragma unroll
            for (int v = 0; v < 4; v++) acc[ni][v] = 0.0f;

#pragma unroll
        for (int ks = 0; ks < 4; ks++) {
#pragma unroll
            for (int ni = 0; ni < 2; ni++) {
                int n = wid * 16 + ni * 8 + lr;
                int o = (n * AT_KPITCH + ks * 16 + lc) * 2;
                uint32_t b0h = *(const uint32_t*)(Kh + o);
                uint32_t b1h = *(const uint32_t*)(Kh + o + 16);
                uint32_t b0l = *(const uint32_t*)(Kl + o);
                uint32_t b1l = *(const uint32_t*)(Kl + o + 16);
                mma16816(acc[ni], qhf[ks][0], qhf[ks][1], qhf[ks][2], qhf[ks][3], b0h, b1h);
                mma16816(acc[ni], qhf[ks][0], qhf[ks][1], qhf[ks][2], qhf[ks][3], b0l, b1l);
                mma16816(acc[ni], qlf[ks][0], qlf[ks][1], qlf[ks][2], qlf[ks][3], b0h, b1h);
            }
        }

#pragma unroll
        for (int ni = 0; ni < 2; ni++) {
            int col = kt * 128 + wid * 16 + ni * 8 + lc;
            float2 v0 = {acc[ni][0] * 0.125f, acc[ni][1] * 0.125f};
            float2 v1 = {acc[ni][2] * 0.125f, acc[ni][3] * 0.125f};
            *(float2*)&S[lr * AT_SPITCH + col] = v0;
            *(float2*)&S[(lr + 8) * AT_SPITCH + col] = v1;
        }
        __syncthreads();
    }

    const int r = tid >> 4, seg = tid & 15;
    const long mrow = ((long)b * SQ + q0 + r) * SQ;

    float mx = -3.4e38f;
#pragma unroll 4
    for (int j = 0; j < 32; j++) {
        int c = seg * 4 + j * 64;
        float4 s4 = *(float4*)&S[r * AT_SPITCH + c];
        uchar4 m4 = *(const uchar4*)(mask8 + mrow + c);
        if (m4.x) s4.x = -1e9f;
        if (m4.y) s4.y = -1e9f;
        if (m4.z) s4.z = -1e9f;
        if (m4.w) s4.w = -1e9f;
        *(float4*)&S[r * AT_SPITCH + c] = s4;
        mx = fmaxf(mx, fmaxf(fmaxf(s4.x, s4.y), fmaxf(s4.z, s4.w)));
    }
    red[r * 16 + seg] = mx;
    __syncthreads();
    float bm = -3.4e38f;
#pragma unroll
    for (int i = 0; i < 16; i++) bm = fmaxf(bm, red[r * 16 + i]);
    __syncthreads();

    float ps = 0.0f;
#pragma unroll 4
    for (int j = 0; j < 32; j++) {
        int c = seg * 4 + j * 64;
        float4 s4 = *(float4*)&S[r * AT_SPITCH + c];
        s4.x = __expf(s4.x - bm); s4.y = __expf(s4.y - bm);
        s4.z = __expf(s4.z - bm); s4.w = __expf(s4.w - bm);
        ps += (s4.x + s4.y) + (s4.z + s4.w);
        *(float4*)&S[r * AT_SPITCH + c] = s4;
    }
    red[r * 16 + seg] = ps;
    __syncthreads();
    float sum = 0.0f;
#pragma unroll
    for (int i = 0; i < 16; i++) sum += red[r * 16 + i];
    if (seg == 0) invs[r] = 1.0f / sum;
    __syncthreads();

    float* orow = attn + ((long)bh * SQ + q0) * SQ;
#pragma unroll 4
    for (int i = 0; i < 32; i++) {
        int u = tid + 256 * i;
        int row = u >> 9;
        int cu = u & 511;
        float4 e4 = *(float4*)&S[row * AT_SPITCH + cu * 4];
        float inv = invs[row];
        e4.x *= inv; e4.y *= inv; e4.z *= inv; e4.w *= inv;
        *(float4*)(orow + (long)u * 4) = e4;
    }
}

// ---------------------------------------------------------------------------
// PV via mma; epilogue writes bf16 hi/lo directly (final GEMM A input).
// ---------------------------------------------------------------------------
#define PV_PF_OFF 0
#define PV_PH_OFF 65536
#define PV_PL_OFF (PV_PH_OFF + 18432)
#define PV_VT_OFF (PV_PL_OFF + 18432)
#define PV_VSTG 18432
#define PV_SMEM (PV_VT_OFF + 2*PV_VSTG)

__global__ __launch_bounds__(256, 1) void pv_mma_kernel(
    const float* __restrict__ attn,
    const __nv_bfloat16* __restrict__ vth, const __nv_bfloat16* __restrict__ vtl,
    __nv_bfloat16* __restrict__ phh, __nv_bfloat16* __restrict__ phl)
{
    extern __shared__ char smem[];
    uint32_t sb = smem_u32(smem);

    const int tid = threadIdx.x;
    const int wid = tid >> 5;
    const int lane = tid & 31;
    const int lr = lane >> 2;
    const int lc = (lane & 3) * 2;
    const int bh = blockIdx.y;
    const int b = bh >> 4, h = bh & 15;
    const int m0 = blockIdx.x * 128;

    auto loadT = [&](int s, int k0) {
        uint32_t pb = sb + PV_PF_OFF + s * 32768;
#pragma unroll
        for (int i = 0; i < 8; i++) {
            int u = tid + 256 * i;
            int row = u >> 4, cu = u & 15;
            cp16(pb + u * 16, attn + ((long)bh * SQ + m0 + row) * SQ + k0 + cu * 4);
        }
        uint32_t vb = sb + PV_VT_OFF + s * PV_VSTG;
#pragma unroll
        for (int i = 0; i < 2; i++) {
            int u = tid + 256 * i;
            int d = u >> 3, cu = u & 7;
            long g = ((long)bh * DKK + d) * SQ + k0 + cu * 8;
            cp16(vb + d * 144 + cu * 16, vth + g);
            cp16(vb + 9216 + d * 144 + cu * 16, vtl + g);
        }
        cp_commit();
    };

    float acc[8][4];
#pragma unroll
    for (int i = 0; i < 8; i++)
#pragma unroll
        for (int v = 0; v < 4; v++) acc[i][v] = 0.0f;

    loadT(0, 0);

    for (int kt = 0; kt < 32; kt++) {
        int s = kt & 1;
        if (kt + 1 < 32) { loadT(s ^ 1, (kt + 1) * 64); cp_wait<1>(); }
        else             { cp_wait<0>(); }
        __syncthreads();

        const float* Pf = (const float*)(smem + PV_PF_OFF + s * 32768);
#pragma unroll
        for (int i = 0; i < 8; i++) {
            int u = tid + 256 * i;
            float4 p = *(const float4*)(Pf + (long)u * 4);
            int row = u >> 4, col = (u & 15) * 4;
            float pv[4] = {p.x, p.y, p.z, p.w};
            unsigned short hh[4], ll[4];
#pragma unroll
            for (int j = 0; j < 4; j++) split_bf16(pv[j], hh[j], ll[j]);
            *(uint2*)(smem + PV_PH_OFF + (row * 72 + col) * 2) = *(uint2*)hh;
            *(uint2*)(smem + PV_PL_OFF + (row * 72 + col) * 2) = *(uint2*)ll;
        }
        __syncthreads();

        const char* Ph = smem + PV_PH_OFF;
        const char* Pl = smem + PV_PL_OFF;
        const char* Vh = smem + PV_VT_OFF + s * PV_VSTG;
        const char* Vl = Vh + 9216;

#pragma unroll
        for (int ks = 0; ks < 4; ks++) {
            int ao = ((wid * 16 + lr) * 72 + ks * 16 + lc) * 2;
            uint32_t ah0 = *(const uint32_t*)(Ph + ao);
            uint32_t ah1 = *(const uint32_t*)(Ph + ao + 8 * 144);
            uint32_t ah2 = *(const uint32_t*)(Ph + ao + 16);
            uint32_t ah3 = *(const uint32_t*)(Ph + ao + 8 * 144 + 16);
            uint32_t al0 = *(const uint32_t*)(Pl + ao);
            uint32_t al1 = *(const uint32_t*)(Pl + ao + 8 * 144);
            uint32_t al2 = *(const uint32_t*)(Pl + ao + 16);
            uint32_t al3 = *(const uint32_t*)(Pl + ao + 8 * 144 + 16);
#pragma unroll
            for (int nt = 0; nt < 8; nt++) {
                int bo = ((nt * 8 + lr) * 72 + ks * 16 + lc) * 2;
                uint32_t b0h = *(const uint32_t*)(Vh + bo);
                uint32_t b1h = *(const uint32_t*)(Vh + bo + 16);
                uint32_t b0l = *(const uint32_t*)(Vl + bo);
                uint32_t b1l = *(const uint32_t*)(Vl + bo + 16);
                mma16816(acc[nt], ah0, ah1, ah2, ah3, b0h, b1h);
                mma16816(acc[nt], ah0, ah1, ah2, ah3, b0l, b1l);
                mma16816(acc[nt], al0, al1, al2, al3, b0h, b1h);
            }
        }
        __syncthreads();
    }

#pragma unroll
    for (int nt = 0; nt < 8; nt++) {
        int row = m0 + wid * 16 + lr;
        int d = nt * 8 + lc;
        long o0 = ((long)(b * SQ + row)) * EMB + h * DKK + d;
        long o1 = o0 + 8L * EMB;
        ushort2 h0, l0, h1, l1;
        split_bf16(acc[nt][0], h0.x, l0.x);
        split_bf16(acc[nt][1], h0.y, l0.y);
        split_bf16(acc[nt][2], h1.x, l1.x);
        split_bf16(acc[nt][3], h1.y, l1.y);
        *(ushort2*)&phh[o0] = h0; *(ushort2*)&phl[o0] = l0;
        *(ushort2*)&phh[o1] = h1; *(ushort2*)&phl[o1] = l1;
    }
}

// ---------------------------------------------------------------------------
extern "C" void kernel_launch(void* const* d_in, const int* in_sizes, int n_in,
                              void* d_out, int out_size)
{
    const float* Q   = (const float*)d_in[0];
    const float* K   = (const float*)d_in[1];
    const float* V   = (const float*)d_in[2];
    const char*  msk = (const char*)d_in[3];
    const float* WQ  = (const float*)d_in[4];
    const float* WK  = (const float*)d_in[5];
    const float* WV  = (const float*)d_in[6];
    const float* Wfc = (const float*)d_in[7];
    float* out = (float*)d_out;

    float *pv, *pfb;
    __nv_bfloat16 *pah, *pal, *pbh, *pbl;
    __nv_bfloat16 *pqh, *pql, *pkh, *pkl, *pvth, *pvtl;
    unsigned char* pm8;
    cudaGetSymbolAddress((void**)&pv,  g_v);
    cudaGetSymbolAddress((void**)&pfb, g_attn_fb);
    cudaGetSymbolAddress((void**)&pah, g_ah);
    cudaGetSymbolAddress((void**)&pal, g_al);
    cudaGetSymbolAddress((void**)&pbh, g_bhT);
    cudaGetSymbolAddress((void**)&pbl, g_blT);
    cudaGetSymbolAddress((void**)&pqh, g_qh);
    cudaGetSymbolAddress((void**)&pql, g_ql);
    cudaGetSymbolAddress((void**)&pkh, g_kh);
    cudaGetSymbolAddress((void**)&pkl, g_kl);
    cudaGetSymbolAddress((void**)&pvth, g_vth);
    cudaGetSymbolAddress((void**)&pvtl, g_vtl);
    cudaGetSymbolAddress((void**)&pm8, g_mask8);

    float* attnbuf = ((long)out_size >= PRED_ELEMS + ATTN_ELEMS)
                         ? (out + PRED_ELEMS) : pfb;

    cudaFuncSetAttribute(gemm_mma_kernel,
                         cudaFuncAttributeMaxDynamicSharedMemorySize, GEMM_SMEM);
    cudaFuncSetAttribute(attn_fused_kernel,
                         cudaFuncAttributeMaxDynamicSharedMemorySize, ATTN_SMEM);
    cudaFuncSetAttribute(pv_mma_kernel,
                         cudaFuncAttributeMaxDynamicSharedMemorySize, PV_SMEM);

    detect_mask_kernel<<<1, 256>>>((const unsigned char*)msk, 65536);
    mask_canon_kernel<<<(unsigned)((MASK_ELEMS / 4 + 255) / 256), 256>>>(msk, pm8, MASK_ELEMS);

    const long AN = (long)BS * EMB;
    dim3 cg((unsigned)((AN / 4 + 255) / 256));
    dim3 tg(EMB / 32, EMB / 32);
    dim3 gg(EMB / 128, BS / 128);

    // Q projection -> split hi/lo directly
    conv_split_kernel<<<cg, 256>>>(Q, pah, pal, AN);
    conv_transpose_kernel<<<tg, 256>>>(WQ, pbh, pbl);
    gemm_mma_kernel<<<gg, 256, GEMM_SMEM>>>(pah, pal, pbh, pbl, nullptr, pqh, pql);

    // K projection -> split hi/lo directly
    conv_split_kernel<<<cg, 256>>>(K, pah, pal, AN);
    conv_transpose_kernel<<<tg, 256>>>(WK, pbh, pbl);
    gemm_mma_kernel<<<gg, 256, GEMM_SMEM>>>(pah, pal, pbh, pbl, nullptr, pkh, pkl);

    // V projection -> fp32 (conv_vt needs strided transpose)
    conv_split_kernel<<<cg, 256>>>(V, pah, pal, AN);
    conv_transpose_kernel<<<tg, 256>>>(WV, pbh, pbl);
    gemm_mma_kernel<<<gg, 256, GEMM_SMEM>>>(pah, pal, pbh, pbl, pv, nullptr, nullptr);
    conv_vt_kernel<<<dim3(SQ / 32, DKK / 32, BH), 256>>>(pv, pvth, pvtl);

    // Fused scores + mask + softmax -> attn
    attn_fused_kernel<<<dim3(SQ / 16, BH), 256, ATTN_SMEM>>>(
        pqh, pql, pkh, pkl, pm8, attnbuf);

    // PV -> split hi/lo directly into final GEMM A buffers
    pv_mma_kernel<<<dim3(SQ / 128, BH), 256, PV_SMEM>>>(attnbuf, pvth, pvtl, pah, pal);

    // Output projection
    conv_transpose_kernel<<<tg, 256>>>(Wfc, pbh, pbl);
    gemm_mma_kernel<<<gg, 256, GEMM_SMEM>>>(pah, pal, pbh, pbl, out, nullptr, nullptr);
}